// round 4
// baseline (speedup 1.0000x reference)
#include <cuda_runtime.h>
#include <cstdint>
#include <cstddef>

// ---------------------------------------------------------------------------
// WaveSubsystem: out = tanh(c@W_mod+b_mod) * (a_diag*w + (w@A_V)@A_U^T)
//                + [c|z]@W_B + b_B
// tf32 mma.sync GEMM chain (4 launches), fused final epilogue.
// R3: resubmit of R2 design (R2 failed on container infra, no kernel signal).
// ---------------------------------------------------------------------------

#define BM 128
#define BN 128
#define BK 32
#define PADA 36   // As row stride (u32): breaks 8-step bank cycle for frag loads
#define PADB 136  // Bs row stride (u32)

// Scratch (allocation-free rule: __device__ globals)
__device__ float g_Y1[4096u * 2048u];
__device__ float g_Y2[4096u * 2048u];
__device__ float g_T [4096u * 512u];

__device__ __forceinline__ uint32_t f2tf32(float x) {
    uint32_t r;
    asm("cvt.rna.tf32.f32 %0, %1;" : "=r"(r) : "f"(x));
    return r;
}

__device__ __forceinline__ void mma_tf32(float c[4],
                                         const uint32_t a[4],
                                         const uint32_t b[2]) {
    asm volatile(
        "mma.sync.aligned.m16n8k8.row.col.f32.tf32.tf32.f32 "
        "{%0,%1,%2,%3}, {%4,%5,%6,%7}, {%8,%9}, {%0,%1,%2,%3};"
        : "+f"(c[0]), "+f"(c[1]), "+f"(c[2]), "+f"(c[3])
        : "r"(a[0]), "r"(a[1]), "r"(a[2]), "r"(a[3]),
          "r"(b[0]), "r"(b[1]));
}

// EPI = 0: C = acc (+bias)      EPI = 1: final fused epilogue
template <bool TRANSB, int EPI>
__global__ __launch_bounds__(256, 2)
void gemm_tf32(int M, int N, int K,
               const float* __restrict__ A1, int lda1, int K1,
               const float* __restrict__ A2, int lda2,
               const float* __restrict__ B, int ldb,
               const float* __restrict__ bias,
               float* __restrict__ C,
               const float* __restrict__ Y1,
               const float* __restrict__ Y2,
               const float* __restrict__ Wp,
               const float* __restrict__ Adiag)
{
    __shared__ uint32_t As[BM][PADA];
    __shared__ uint32_t Bs[BK][PADB];

    const int tid  = threadIdx.x;
    const int lane = tid & 31;
    const int warp = tid >> 5;
    const int wm   = warp & 3;   // 4 warps along M (32 rows each)
    const int wn   = warp >> 2;  // 2 warps along N (64 cols each)
    const int g    = lane >> 2;  // groupID 0..7
    const int tg   = lane & 3;   // threadID_in_group 0..3

    const int m0 = blockIdx.y * BM;
    const int n0 = blockIdx.x * BN;

    float acc[2][8][4];
    #pragma unroll
    for (int mi = 0; mi < 2; mi++)
        #pragma unroll
        for (int ni = 0; ni < 8; ni++)
            #pragma unroll
            for (int j = 0; j < 4; j++) acc[mi][ni][j] = 0.f;

    #pragma unroll 1
    for (int k0 = 0; k0 < K; k0 += BK) {
        // ---- load A tile [BM x BK], convert to tf32 ----
        const float* Asrc = A1;
        int lda = lda1, kk0 = k0;
        if (A2 != nullptr && k0 >= K1) { Asrc = A2; lda = lda2; kk0 = k0 - K1; }
        #pragma unroll
        for (int i = 0; i < 4; i++) {
            int lin = tid + i * 256;          // 0..1023
            int r   = lin >> 3;               // 0..127
            int c4  = (lin & 7) * 4;          // 0,4,..,28
            const float4 v = *reinterpret_cast<const float4*>(
                &Asrc[(size_t)(m0 + r) * lda + kk0 + c4]);
            As[r][c4 + 0] = f2tf32(v.x);
            As[r][c4 + 1] = f2tf32(v.y);
            As[r][c4 + 2] = f2tf32(v.z);
            As[r][c4 + 3] = f2tf32(v.w);
        }
        // ---- load B tile [BK x BN] ----
        if (!TRANSB) {
            #pragma unroll
            for (int i = 0; i < 4; i++) {
                int lin = tid + i * 256;      // 0..1023
                int r   = lin >> 5;           // 0..31
                int c4  = (lin & 31) * 4;     // 0..124
                const float4 v = *reinterpret_cast<const float4*>(
                    &B[(size_t)(k0 + r) * ldb + n0 + c4]);
                Bs[r][c4 + 0] = f2tf32(v.x);
                Bs[r][c4 + 1] = f2tf32(v.y);
                Bs[r][c4 + 2] = f2tf32(v.z);
                Bs[r][c4 + 3] = f2tf32(v.w);
            }
        } else {
            // Bs[k][n] = B[(n0+n)*ldb + k0+k]  (B stored [N x K] row-major)
            #pragma unroll
            for (int i = 0; i < 16; i++) {
                int lin = tid + i * 256;      // 0..4095
                int r   = lin & 31;           // k within tile (coalesced along K)
                int c   = lin >> 5;           // n within tile 0..127
                Bs[r][c] = f2tf32(B[(size_t)(n0 + c) * ldb + k0 + r]);
            }
        }
        __syncthreads();

        // ---- compute: 4 k-steps of m16n8k8 ----
        #pragma unroll
        for (int ks = 0; ks < BK / 8; ks++) {
            uint32_t af[2][4];
            #pragma unroll
            for (int mi = 0; mi < 2; mi++) {
                int r = wm * 32 + mi * 16 + g;
                af[mi][0] = As[r    ][ks * 8 + tg    ];
                af[mi][1] = As[r + 8][ks * 8 + tg    ];
                af[mi][2] = As[r    ][ks * 8 + tg + 4];
                af[mi][3] = As[r + 8][ks * 8 + tg + 4];
            }
            uint32_t bf[8][2];
            #pragma unroll
            for (int ni = 0; ni < 8; ni++) {
                int c = wn * 64 + ni * 8 + g;
                bf[ni][0] = Bs[ks * 8 + tg    ][c];
                bf[ni][1] = Bs[ks * 8 + tg + 4][c];
            }
            #pragma unroll
            for (int mi = 0; mi < 2; mi++)
                #pragma unroll
                for (int ni = 0; ni < 8; ni++)
                    mma_tf32(acc[mi][ni], af[mi], bf[ni]);
        }
        __syncthreads();
    }

    // ---- epilogue ----
    #pragma unroll
    for (int mi = 0; mi < 2; mi++) {
        #pragma unroll
        for (int rr = 0; rr < 2; rr++) {
            int row = m0 + wm * 32 + mi * 16 + g + rr * 8;
            #pragma unroll
            for (int ni = 0; ni < 8; ni++) {
                int col = n0 + wn * 64 + ni * 8 + tg * 2;
                size_t idx = (size_t)row * N + col;
                float v0 = acc[mi][ni][rr * 2 + 0];
                float v1 = acc[mi][ni][rr * 2 + 1];
                if (EPI == 0) {
                    if (bias != nullptr) {
                        v0 += bias[col];
                        v1 += bias[col + 1];
                    }
                    *reinterpret_cast<float2*>(&C[idx]) = make_float2(v0, v1);
                } else {
                    float2 y1 = *reinterpret_cast<const float2*>(&Y1[idx]);
                    float2 y2 = *reinterpret_cast<const float2*>(&Y2[idx]);
                    float2 w  = *reinterpret_cast<const float2*>(&Wp[idx]);
                    float ad0 = tanhf(Adiag[col])     * 0.9f;
                    float ad1 = tanhf(Adiag[col + 1]) * 0.9f;
                    float o0 = tanhf(y1.x) * (ad0 * w.x + v0) + y2.x;
                    float o1 = tanhf(y1.y) * (ad1 * w.y + v1) + y2.y;
                    *reinterpret_cast<float2*>(&C[idx]) = make_float2(o0, o1);
                }
            }
        }
    }
}

extern "C" void kernel_launch(void* const* d_in, const int* in_sizes, int n_in,
                              void* d_out, int out_size)
{
    const float* w_prev = (const float*)d_in[0];   // [4096,2048]
    const float* z_t    = (const float*)d_in[1];   // [4096,2048]
    const float* c_t    = (const float*)d_in[2];   // [4096,1024]
    const float* A_diag = (const float*)d_in[3];   // [2048]
    const float* A_U    = (const float*)d_in[4];   // [2048,512]
    const float* A_V    = (const float*)d_in[5];   // [2048,512]
    const float* W_mod  = (const float*)d_in[6];   // [1024,2048]
    const float* b_mod  = (const float*)d_in[7];   // [2048]
    const float* W_B    = (const float*)d_in[8];   // [3072,2048]
    const float* b_B    = (const float*)d_in[9];   // [2048]
    float* out = (float*)d_out;                    // [4096,2048]

    const int Bsz = 4096, DW = 2048, DC = 1024, DP = 2048, R = 512;
    (void)in_sizes; (void)n_in; (void)out_size; (void)DP;

    float *Y1, *Y2, *T;
    cudaGetSymbolAddress((void**)&Y1, g_Y1);
    cudaGetSymbolAddress((void**)&Y2, g_Y2);
    cudaGetSymbolAddress((void**)&T,  g_T);

    dim3 blk(256);

    // 1) Y1 = c_t @ W_mod + b_mod   [4096 x 2048], K=1024
    gemm_tf32<false, 0><<<dim3(DW / BN, Bsz / BM), blk>>>(
        Bsz, DW, DC, c_t, DC, DC, nullptr, 0,
        W_mod, DW, b_mod, Y1, nullptr, nullptr, nullptr, nullptr);

    // 2) Y2 = [c_t | z_t] @ W_B + b_B   [4096 x 2048], K=3072 (split A)
    gemm_tf32<false, 0><<<dim3(DW / BN, Bsz / BM), blk>>>(
        Bsz, DW, DC + DP, c_t, DC, DC, z_t, DP,
        W_B, DW, b_B, Y2, nullptr, nullptr, nullptr, nullptr);

    // 3) T = w_prev @ A_V   [4096 x 512], K=2048
    gemm_tf32<false, 0><<<dim3(R / BN, Bsz / BM), blk>>>(
        Bsz, R, DW, w_prev, DW, DW, nullptr, 0,
        A_V, R, nullptr, T, nullptr, nullptr, nullptr, nullptr);

    // 4) out = tanh(Y1) * (a_diag*w_prev + T @ A_U^T) + Y2   [4096 x 2048], K=512
    gemm_tf32<true, 1><<<dim3(DW / BN, Bsz / BM), blk>>>(
        Bsz, DW, R, T, R, R, nullptr, 0,
        A_U, R, nullptr, out, Y1, Y2, w_prev, A_diag);
}

// round 6
// speedup vs baseline: 1.4174x; 1.4174x over previous
#include <cuda_runtime.h>
#include <cstdint>
#include <cstddef>

// ============================================================================
// WaveSubsystem, sm_103 legacy-tensor path (tcgen05 unavailable: harness PTX
// targets sm_103, not sm_103a — R5 evidence).
//   out = tanh(c@W_mod+b_mod) * (tanh(A_diag)*0.9*w + (w@A_V)@A_U^T) + [c|z]@W_B + b_B
// One unified tf32 mma.sync GEMM (A [M,K], B [N,K] both K-major) with 2-stage
// cp.async double buffering. Precision-critical operands RNA-pre-rounded.
// ============================================================================

#define BM 128
#define BN 128
#define BK 32
#define STAGE_BYTES 32768          // A 16KB + B 16KB
#define SMEM_TOTAL  65536

// ---------------- scratch (__device__ globals; allocation-free rule) --------
__device__ float g_CZ [4096ull*3072];   // rounded [c|z]
__device__ float g_WmT[2048ull*1024];   // rounded W_mod^T [N,K]
__device__ float g_WBT[2048ull*3072];   // rounded W_B^T   [N,K]
__device__ float g_AVT[ 512ull*2048];   // rounded A_V^T   [N,K]
__device__ float g_Y1 [4096ull*2048];   // tanh(c@W_mod+b_mod)
__device__ float g_Y2 [4096ull*2048];
__device__ float g_T  [4096ull*512];    // rounded w@A_V

// ---------------- helpers ---------------------------------------------------
__device__ __forceinline__ uint32_t smem_u32(const void* p) {
    uint32_t a;
    asm("{ .reg .u64 t; cvta.to.shared.u64 t, %1; cvt.u32.u64 %0, t; }"
        : "=r"(a) : "l"(p));
    return a;
}
__device__ __forceinline__ uint32_t f2tf32(float x) {
    uint32_t r;
    asm("cvt.rna.tf32.f32 %0, %1;" : "=r"(r) : "f"(x));
    return r;
}
#define CP_ASYNC16(dst, src) \
    asm volatile("cp.async.cg.shared.global [%0], [%1], 16;" :: "r"(dst), "l"(src))
#define CP_COMMIT()  asm volatile("cp.async.commit_group;" ::: "memory")
#define CP_WAIT(n)   asm volatile("cp.async.wait_group %0;" :: "n"(n) : "memory")

__device__ __forceinline__ void mma_tf32(float c[4],
                                         const uint32_t a[4],
                                         const uint32_t b[2]) {
    asm volatile(
        "mma.sync.aligned.m16n8k8.row.col.f32.tf32.tf32.f32 "
        "{%0,%1,%2,%3}, {%4,%5,%6,%7}, {%8,%9}, {%0,%1,%2,%3};"
        : "+f"(c[0]), "+f"(c[1]), "+f"(c[2]), "+f"(c[3])
        : "r"(a[0]), "r"(a[1]), "r"(a[2]), "r"(a[3]),
          "r"(b[0]), "r"(b[1]));
}

// ---------------- pre-pass kernels ------------------------------------------
__global__ void round_cat(const float4* __restrict__ in, uint4* __restrict__ out,
                          int n4, int os4, int off4, int total4) {
    int i = blockIdx.x * blockDim.x + threadIdx.x;
    if (i >= total4) return;
    int m = i / n4, k = i - m * n4;
    float4 v = in[i];
    uint4 r;
    r.x = f2tf32(v.x); r.y = f2tf32(v.y); r.z = f2tf32(v.z); r.w = f2tf32(v.w);
    out[(size_t)m * os4 + off4 + k] = r;
}

// transpose + round: in [R,C] -> out [C,R]
__global__ void transpose_rnd(const float* __restrict__ in, uint32_t* __restrict__ out,
                              int R, int C) {
    __shared__ float t[32][33];
    int x  = blockIdx.x * 32 + threadIdx.x;
    int y0 = blockIdx.y * 32;
    #pragma unroll
    for (int j = 0; j < 32; j += 8)
        t[threadIdx.y + j][threadIdx.x] = in[(size_t)(y0 + threadIdx.y + j) * C + x];
    __syncthreads();
    int ox  = y0 + threadIdx.x;
    int oy0 = blockIdx.x * 32;
    #pragma unroll
    for (int j = 0; j < 32; j += 8)
        out[(size_t)(oy0 + threadIdx.y + j) * R + ox] = f2tf32(t[threadIdx.x][threadIdx.y + j]);
}

// ---------------- unified GEMM: C[M,N] = A[M,K] @ B[N,K]^T ------------------
// smem layout per stage: rows of 128B (32 floats) with 16B-granule xor swizzle
//   addr(row,k) = row*128 + ((k>>2 ^ (row&7))<<4) + (k&3)*4
// EPI: 0 = +bias  |  1 = rna-round  |  2 = final fused  |  3 = tanh(+bias)
template <int EPI>
__global__ __launch_bounds__(256, 2)
void gemm_ms(int N_total, int K, int lda,
             const float* __restrict__ A, const float* __restrict__ B,
             const float* __restrict__ bias, float* __restrict__ C,
             const float* __restrict__ Ey1, const float* __restrict__ Ey2,
             const float* __restrict__ Ew, const float* __restrict__ Ead)
{
    extern __shared__ __align__(128) char sm[];
    const uint32_t sb = smem_u32(sm);
    const int tid  = threadIdx.x;
    const int warp = tid >> 5, lane = tid & 31;
    const int wm = warp & 3, wn = warp >> 2;       // 4x2 warps, 32x64 tiles
    const int g  = lane >> 2, tg = lane & 3;
    const int m0 = blockIdx.y * BM, n0 = blockIdx.x * BN;

    // producer addresses: 4 x 16B granules each for A and B per thread
    const float* pA[4]; const float* pB[4];
    uint32_t dA[4], dB[4];
    #pragma unroll
    for (int i = 0; i < 4; i++) {
        int q = tid + (i << 8), r = q >> 3, j = q & 7;
        pA[i] = A + (size_t)(m0 + r) * lda + (j << 2);
        dA[i] = r * 128 + ((j ^ (r & 7)) << 4);
        pB[i] = B + (size_t)(n0 + r) * K + (j << 2);
        dB[i] = 16384u + r * 128 + ((j ^ (r & 7)) << 4);
    }

    float acc[2][8][4];
    #pragma unroll
    for (int mi = 0; mi < 2; mi++)
        #pragma unroll
        for (int ni = 0; ni < 8; ni++)
            #pragma unroll
            for (int j = 0; j < 4; j++) acc[mi][ni][j] = 0.f;

    const int KT = K >> 5;
    int stg = 0;
    auto produce = [&]() {
        uint32_t base = sb + (uint32_t)(stg & 1) * STAGE_BYTES;
        #pragma unroll
        for (int i = 0; i < 4; i++) { CP_ASYNC16(base + dA[i], pA[i]); pA[i] += BK; }
        #pragma unroll
        for (int i = 0; i < 4; i++) { CP_ASYNC16(base + dB[i], pB[i]); pB[i] += BK; }
        CP_COMMIT();
        stg++;
    };

    produce();                         // stage 0
    #pragma unroll 1
    for (int kt = 0; kt < KT; kt++) {
        if (kt + 1 < KT) { produce(); CP_WAIT(1); }
        else             { CP_WAIT(0); }
        __syncthreads();

        const uint32_t* sA = (const uint32_t*)(sm + (kt & 1) * STAGE_BYTES);
        const uint32_t* sB = sA + 4096;

        #pragma unroll
        for (int ks = 0; ks < 4; ks++) {
            const int s0 = (((ks * 2)     ^ g) << 2) + tg;   // u32 idx in row
            const int s1 = (((ks * 2 + 1) ^ g) << 2) + tg;
            uint32_t af[2][4];
            #pragma unroll
            for (int mi = 0; mi < 2; mi++) {
                int r = wm * 32 + mi * 16 + g;
                af[mi][0] = sA[r * 32 + s0];
                af[mi][1] = sA[(r + 8) * 32 + s0];
                af[mi][2] = sA[r * 32 + s1];
                af[mi][3] = sA[(r + 8) * 32 + s1];
            }
            uint32_t bf[8][2];
            #pragma unroll
            for (int ni = 0; ni < 8; ni++) {
                int n = wn * 64 + ni * 8 + g;
                bf[ni][0] = sB[n * 32 + s0];
                bf[ni][1] = sB[n * 32 + s1];
            }
            #pragma unroll
            for (int mi = 0; mi < 2; mi++)
                #pragma unroll
                for (int ni = 0; ni < 8; ni++)
                    mma_tf32(acc[mi][ni], af[mi], bf[ni]);
        }
        __syncthreads();               // buffer free before overwrite
    }

    // ---- epilogue (register-direct, 8B-granule coalesced sectors) ----
    #pragma unroll
    for (int mi = 0; mi < 2; mi++) {
        #pragma unroll
        for (int rr = 0; rr < 2; rr++) {
            int row = m0 + wm * 32 + mi * 16 + g + rr * 8;
            #pragma unroll
            for (int ni = 0; ni < 8; ni++) {
                int col = n0 + wn * 64 + ni * 8 + tg * 2;
                size_t idx = (size_t)row * N_total + col;
                float v0 = acc[mi][ni][rr * 2 + 0];
                float v1 = acc[mi][ni][rr * 2 + 1];
                if (EPI == 0) {
                    v0 += bias[col]; v1 += bias[col + 1];
                    *reinterpret_cast<float2*>(&C[idx]) = make_float2(v0, v1);
                } else if (EPI == 3) {
                    v0 = tanhf(v0 + bias[col]); v1 = tanhf(v1 + bias[col + 1]);
                    *reinterpret_cast<float2*>(&C[idx]) = make_float2(v0, v1);
                } else if (EPI == 1) {
                    uint2 r2; r2.x = f2tf32(v0); r2.y = f2tf32(v1);
                    *reinterpret_cast<uint2*>(&C[idx]) = r2;
                } else {
                    float2 y1 = *reinterpret_cast<const float2*>(&Ey1[idx]);
                    float2 y2 = *reinterpret_cast<const float2*>(&Ey2[idx]);
                    float2 w  = *reinterpret_cast<const float2*>(&Ew[idx]);
                    float ad0 = tanhf(Ead[col])     * 0.9f;
                    float ad1 = tanhf(Ead[col + 1]) * 0.9f;
                    float o0 = y1.x * (ad0 * w.x + v0) + y2.x;
                    float o1 = y1.y * (ad1 * w.y + v1) + y2.y;
                    *reinterpret_cast<float2*>(&C[idx]) = make_float2(o0, o1);
                }
            }
        }
    }
}

// ---------------- host ------------------------------------------------------
extern "C" void kernel_launch(void* const* d_in, const int* in_sizes, int n_in,
                              void* d_out, int out_size)
{
    const float* w_prev = (const float*)d_in[0];   // [4096,2048]
    const float* z_t    = (const float*)d_in[1];   // [4096,2048]
    const float* c_t    = (const float*)d_in[2];   // [4096,1024]
    const float* A_diag = (const float*)d_in[3];   // [2048]
    const float* A_U    = (const float*)d_in[4];   // [2048,512]  already [N,K]
    const float* A_V    = (const float*)d_in[5];   // [2048,512]
    const float* W_mod  = (const float*)d_in[6];   // [1024,2048]
    const float* b_mod  = (const float*)d_in[7];
    const float* W_B    = (const float*)d_in[8];   // [3072,2048]
    const float* b_B    = (const float*)d_in[9];
    float* out = (float*)d_out;                    // [4096,2048]
    (void)in_sizes; (void)n_in; (void)out_size;

    float *CZ, *WmT, *WBT, *AVT, *Y1, *Y2, *T;
    cudaGetSymbolAddress((void**)&CZ,  g_CZ);
    cudaGetSymbolAddress((void**)&WmT, g_WmT);
    cudaGetSymbolAddress((void**)&WBT, g_WBT);
    cudaGetSymbolAddress((void**)&AVT, g_AVT);
    cudaGetSymbolAddress((void**)&Y1,  g_Y1);
    cudaGetSymbolAddress((void**)&Y2,  g_Y2);
    cudaGetSymbolAddress((void**)&T,   g_T);

    cudaFuncSetAttribute(gemm_ms<0>, cudaFuncAttributeMaxDynamicSharedMemorySize, SMEM_TOTAL);
    cudaFuncSetAttribute(gemm_ms<1>, cudaFuncAttributeMaxDynamicSharedMemorySize, SMEM_TOTAL);
    cudaFuncSetAttribute(gemm_ms<2>, cudaFuncAttributeMaxDynamicSharedMemorySize, SMEM_TOTAL);
    cudaFuncSetAttribute(gemm_ms<3>, cudaFuncAttributeMaxDynamicSharedMemorySize, SMEM_TOTAL);

    // pre-passes: RNA-round + concat activations; round+transpose weights to [N,K]
    round_cat<<<4096, 256>>>((const float4*)c_t, (uint4*)CZ, 256, 768, 0,   1048576);
    round_cat<<<8192, 256>>>((const float4*)z_t, (uint4*)CZ, 512, 768, 256, 2097152);
    transpose_rnd<<<dim3(64, 32), dim3(32, 8)>>>(W_mod, (uint32_t*)WmT, 1024, 2048);
    transpose_rnd<<<dim3(64, 96), dim3(32, 8)>>>(W_B,   (uint32_t*)WBT, 3072, 2048);
    transpose_rnd<<<dim3(16, 64), dim3(32, 8)>>>(A_V,   (uint32_t*)AVT, 2048, 512);

    // G1: Y1 = tanh(CZ[:, :1024] @ WmT^T + b_mod)
    gemm_ms<3><<<dim3(16, 32), 256, SMEM_TOTAL>>>(2048, 1024, 3072, CZ, WmT, b_mod, Y1,
                                                  nullptr, nullptr, nullptr, nullptr);
    // G2: Y2 = CZ @ WBT^T + b_B
    gemm_ms<0><<<dim3(16, 32), 256, SMEM_TOTAL>>>(2048, 3072, 3072, CZ, WBT, b_B, Y2,
                                                  nullptr, nullptr, nullptr, nullptr);
    // G3: T = rna(w_prev @ AVT^T)   (w_prev raw: truncation bias attenuated 10x)
    gemm_ms<1><<<dim3(4, 32), 256, SMEM_TOTAL>>>(512, 2048, 2048, w_prev, AVT, nullptr, T,
                                                 nullptr, nullptr, nullptr, nullptr);
    // G4: out = Y1 * (tanh(A_diag)*0.9*w_prev + T @ A_U^T) + Y2
    gemm_ms<2><<<dim3(16, 32), 256, SMEM_TOTAL>>>(2048, 512, 512, T, A_U, nullptr, out,
                                                  Y1, Y2, w_prev, A_diag);
}

// round 7
// speedup vs baseline: 1.5039x; 1.0611x over previous
#include <cuda_runtime.h>
#include <cstdint>
#include <cstddef>

// ============================================================================
// WaveSubsystem, sm_103 legacy-tensor path (tcgen05 not available via harness
// toolchain: PTX targets sm_103 plain — R5 evidence).
//   out = tanh(c@W_mod+b_mod) * (tanh(A_diag)*0.9*w + (w@A_V)@A_U^T) + [c|z]@W_B + b_B
// R7: 64x64 warp tile (8 MAC/B smem ratio, was 5.33), 3-stage cp.async ring
// with one barrier per k-tile. CTA 128x128, 4 warps, 2 CTAs/SM.
// ============================================================================

#define BM 128
#define BN 128
#define BK 32
#define STAGE_BYTES 32768          // A 16KB + B 16KB
#define NSTAGE 3
#define SMEM_TOTAL (STAGE_BYTES * NSTAGE)

// ---------------- scratch (__device__ globals; allocation-free rule) --------
__device__ float g_CZ [4096ull*3072];   // rounded [c|z]
__device__ float g_WmT[2048ull*1024];   // rounded W_mod^T [N,K]
__device__ float g_WBT[2048ull*3072];   // rounded W_B^T   [N,K]
__device__ float g_AVT[ 512ull*2048];   // rounded A_V^T   [N,K]
__device__ float g_Y1 [4096ull*2048];   // tanh(c@W_mod+b_mod)
__device__ float g_Y2 [4096ull*2048];
__device__ float g_T  [4096ull*512];    // rounded w@A_V

// ---------------- helpers ---------------------------------------------------
__device__ __forceinline__ uint32_t smem_u32(const void* p) {
    uint32_t a;
    asm("{ .reg .u64 t; cvta.to.shared.u64 t, %1; cvt.u32.u64 %0, t; }"
        : "=r"(a) : "l"(p));
    return a;
}
__device__ __forceinline__ uint32_t f2tf32(float x) {
    uint32_t r;
    asm("cvt.rna.tf32.f32 %0, %1;" : "=r"(r) : "f"(x));
    return r;
}
#define CP_ASYNC16(dst, src) \
    asm volatile("cp.async.cg.shared.global [%0], [%1], 16;" :: "r"(dst), "l"(src))
#define CP_COMMIT()  asm volatile("cp.async.commit_group;" ::: "memory")
#define CP_WAIT(n)   asm volatile("cp.async.wait_group %0;" :: "n"(n) : "memory")

__device__ __forceinline__ void mma_tf32(float c[4],
                                         const uint32_t a[4],
                                         const uint32_t b[2]) {
    asm volatile(
        "mma.sync.aligned.m16n8k8.row.col.f32.tf32.tf32.f32 "
        "{%0,%1,%2,%3}, {%4,%5,%6,%7}, {%8,%9}, {%0,%1,%2,%3};"
        : "+f"(c[0]), "+f"(c[1]), "+f"(c[2]), "+f"(c[3])
        : "r"(a[0]), "r"(a[1]), "r"(a[2]), "r"(a[3]),
          "r"(b[0]), "r"(b[1]));
}

// ---------------- pre-pass kernels ------------------------------------------
__global__ void round_cat(const float4* __restrict__ in, uint4* __restrict__ out,
                          int n4, int os4, int off4, int total4) {
    int i = blockIdx.x * blockDim.x + threadIdx.x;
    if (i >= total4) return;
    int m = i / n4, k = i - m * n4;
    float4 v = in[i];
    uint4 r;
    r.x = f2tf32(v.x); r.y = f2tf32(v.y); r.z = f2tf32(v.z); r.w = f2tf32(v.w);
    out[(size_t)m * os4 + off4 + k] = r;
}

// transpose + round: in [R,C] -> out [C,R]
__global__ void transpose_rnd(const float* __restrict__ in, uint32_t* __restrict__ out,
                              int R, int C) {
    __shared__ float t[32][33];
    int x  = blockIdx.x * 32 + threadIdx.x;
    int y0 = blockIdx.y * 32;
    #pragma unroll
    for (int j = 0; j < 32; j += 8)
        t[threadIdx.y + j][threadIdx.x] = in[(size_t)(y0 + threadIdx.y + j) * C + x];
    __syncthreads();
    int ox  = y0 + threadIdx.x;
    int oy0 = blockIdx.x * 32;
    #pragma unroll
    for (int j = 0; j < 32; j += 8)
        out[(size_t)(oy0 + threadIdx.y + j) * R + ox] = f2tf32(t[threadIdx.x][threadIdx.y + j]);
}

// ---------------- unified GEMM: C[M,N] = A[M,K] @ B[N,K]^T ------------------
// smem per stage: 128B rows, 16B-granule xor swizzle
//   addr(row,k) = row*128 + ((k>>2 ^ (row&7))<<4) + (k&3)*4
// 4 warps (2x2), warp tile 64x64. EPI: 0=+bias 1=rna 2=final-fused 3=tanh(+bias)
template <int EPI>
__global__ __launch_bounds__(128, 2)
void gemm_ms(int N_total, int K, int lda,
             const float* __restrict__ A, const float* __restrict__ B,
             const float* __restrict__ bias, float* __restrict__ C,
             const float* __restrict__ Ey1, const float* __restrict__ Ey2,
             const float* __restrict__ Ew, const float* __restrict__ Ead)
{
    extern __shared__ __align__(128) char sm[];
    const uint32_t sb = smem_u32(sm);
    const int tid  = threadIdx.x;
    const int warp = tid >> 5, lane = tid & 31;
    const int wm = warp & 1, wn = warp >> 1;       // 2x2 warps, 64x64 tiles
    const int g  = lane >> 2, tg = lane & 3;
    const int m0 = blockIdx.y * BM, n0 = blockIdx.x * BN;

    // producer: 8 A granules + 8 B granules (16B each) per thread per k-tile
    const float* pA[8]; const float* pB[8];
    uint32_t dA[8], dB[8];
    #pragma unroll
    for (int i = 0; i < 8; i++) {
        int q = tid + (i << 7), r = q >> 3, j = q & 7;
        pA[i] = A + (size_t)(m0 + r) * lda + (j << 2);
        dA[i] = r * 128 + ((j ^ (r & 7)) << 4);
        pB[i] = B + (size_t)(n0 + r) * K + (j << 2);
        dB[i] = 16384u + r * 128 + ((j ^ (r & 7)) << 4);
    }

    float acc[4][8][4];
    #pragma unroll
    for (int mi = 0; mi < 4; mi++)
        #pragma unroll
        for (int ni = 0; ni < 8; ni++)
            #pragma unroll
            for (int j = 0; j < 4; j++) acc[mi][ni][j] = 0.f;

    const int KT = K >> 5;
    auto produce = [&](int kt) {
        uint32_t base = sb + (uint32_t)(kt % NSTAGE) * STAGE_BYTES;
        int ko = kt << 5;
        #pragma unroll
        for (int i = 0; i < 8; i++) CP_ASYNC16(base + dA[i], pA[i] + ko);
        #pragma unroll
        for (int i = 0; i < 8; i++) CP_ASYNC16(base + dB[i], pB[i] + ko);
        CP_COMMIT();
    };

    produce(0);
    produce(1);                                    // all K here are >= 64
    #pragma unroll 1
    for (int kt = 0; kt < KT; kt++) {
        if (kt == KT - 1) { CP_WAIT(0); } else { CP_WAIT(1); }
        __syncthreads();                           // one barrier per k-tile:
        if (kt + 2 < KT) produce(kt + 2);          // overwrites stage (kt-1)%3,
                                                   // released by this barrier
        const uint32_t* sA = (const uint32_t*)(sm + (kt % NSTAGE) * STAGE_BYTES);
        const uint32_t* sB = sA + 4096;

        #pragma unroll
        for (int ks = 0; ks < 4; ks++) {
            const int s0 = (((ks * 2)     ^ g) << 2) + tg;
            const int s1 = (((ks * 2 + 1) ^ g) << 2) + tg;
            uint32_t bf[8][2];
            #pragma unroll
            for (int ni = 0; ni < 8; ni++) {
                int n = wn * 64 + ni * 8 + g;
                bf[ni][0] = sB[n * 32 + s0];
                bf[ni][1] = sB[n * 32 + s1];
            }
            #pragma unroll
            for (int mi = 0; mi < 4; mi++) {
                int r = wm * 64 + mi * 16 + g;
                uint32_t af[4];
                af[0] = sA[r * 32 + s0];
                af[1] = sA[(r + 8) * 32 + s0];
                af[2] = sA[r * 32 + s1];
                af[3] = sA[(r + 8) * 32 + s1];
                #pragma unroll
                for (int ni = 0; ni < 8; ni++)
                    mma_tf32(acc[mi][ni], af, bf[ni]);
            }
        }
    }

    // ---- epilogue (register-direct, 8B-granule sectors) ----
    #pragma unroll
    for (int mi = 0; mi < 4; mi++) {
        #pragma unroll
        for (int rr = 0; rr < 2; rr++) {
            int row = m0 + wm * 64 + mi * 16 + g + rr * 8;
            #pragma unroll
            for (int ni = 0; ni < 8; ni++) {
                int col = n0 + wn * 64 + ni * 8 + tg * 2;
                size_t idx = (size_t)row * N_total + col;
                float v0 = acc[mi][ni][rr * 2 + 0];
                float v1 = acc[mi][ni][rr * 2 + 1];
                if (EPI == 0) {
                    v0 += bias[col]; v1 += bias[col + 1];
                    *reinterpret_cast<float2*>(&C[idx]) = make_float2(v0, v1);
                } else if (EPI == 3) {
                    v0 = tanhf(v0 + bias[col]); v1 = tanhf(v1 + bias[col + 1]);
                    *reinterpret_cast<float2*>(&C[idx]) = make_float2(v0, v1);
                } else if (EPI == 1) {
                    uint2 r2; r2.x = f2tf32(v0); r2.y = f2tf32(v1);
                    *reinterpret_cast<uint2*>(&C[idx]) = r2;
                } else {
                    float2 y1 = *reinterpret_cast<const float2*>(&Ey1[idx]);
                    float2 y2 = *reinterpret_cast<const float2*>(&Ey2[idx]);
                    float2 w  = *reinterpret_cast<const float2*>(&Ew[idx]);
                    float ad0 = tanhf(Ead[col])     * 0.9f;
                    float ad1 = tanhf(Ead[col + 1]) * 0.9f;
                    float o0 = y1.x * (ad0 * w.x + v0) + y2.x;
                    float o1 = y1.y * (ad1 * w.y + v1) + y2.y;
                    *reinterpret_cast<float2*>(&C[idx]) = make_float2(o0, o1);
                }
            }
        }
    }
}

// ---------------- host ------------------------------------------------------
extern "C" void kernel_launch(void* const* d_in, const int* in_sizes, int n_in,
                              void* d_out, int out_size)
{
    const float* w_prev = (const float*)d_in[0];   // [4096,2048]
    const float* z_t    = (const float*)d_in[1];   // [4096,2048]
    const float* c_t    = (const float*)d_in[2];   // [4096,1024]
    const float* A_diag = (const float*)d_in[3];   // [2048]
    const float* A_U    = (const float*)d_in[4];   // [2048,512]  already [N,K]
    const float* A_V    = (const float*)d_in[5];   // [2048,512]
    const float* W_mod  = (const float*)d_in[6];   // [1024,2048]
    const float* b_mod  = (const float*)d_in[7];
    const float* W_B    = (const float*)d_in[8];   // [3072,2048]
    const float* b_B    = (const float*)d_in[9];
    float* out = (float*)d_out;                    // [4096,2048]
    (void)in_sizes; (void)n_in; (void)out_size;

    float *CZ, *WmT, *WBT, *AVT, *Y1, *Y2, *T;
    cudaGetSymbolAddress((void**)&CZ,  g_CZ);
    cudaGetSymbolAddress((void**)&WmT, g_WmT);
    cudaGetSymbolAddress((void**)&WBT, g_WBT);
    cudaGetSymbolAddress((void**)&AVT, g_AVT);
    cudaGetSymbolAddress((void**)&Y1,  g_Y1);
    cudaGetSymbolAddress((void**)&Y2,  g_Y2);
    cudaGetSymbolAddress((void**)&T,   g_T);

    cudaFuncSetAttribute(gemm_ms<0>, cudaFuncAttributeMaxDynamicSharedMemorySize, SMEM_TOTAL);
    cudaFuncSetAttribute(gemm_ms<1>, cudaFuncAttributeMaxDynamicSharedMemorySize, SMEM_TOTAL);
    cudaFuncSetAttribute(gemm_ms<2>, cudaFuncAttributeMaxDynamicSharedMemorySize, SMEM_TOTAL);
    cudaFuncSetAttribute(gemm_ms<3>, cudaFuncAttributeMaxDynamicSharedMemorySize, SMEM_TOTAL);

    // pre-passes: RNA-round + concat activations; round+transpose weights to [N,K]
    round_cat<<<4096, 256>>>((const float4*)c_t, (uint4*)CZ, 256, 768, 0,   1048576);
    round_cat<<<8192, 256>>>((const float4*)z_t, (uint4*)CZ, 512, 768, 256, 2097152);
    transpose_rnd<<<dim3(64, 32), dim3(32, 8)>>>(W_mod, (uint32_t*)WmT, 1024, 2048);
    transpose_rnd<<<dim3(64, 96), dim3(32, 8)>>>(W_B,   (uint32_t*)WBT, 3072, 2048);
    transpose_rnd<<<dim3(16, 64), dim3(32, 8)>>>(A_V,   (uint32_t*)AVT, 2048, 512);

    // G1: Y1 = tanh(CZ[:, :1024] @ WmT^T + b_mod)
    gemm_ms<3><<<dim3(16, 32), 128, SMEM_TOTAL>>>(2048, 1024, 3072, CZ, WmT, b_mod, Y1,
                                                  nullptr, nullptr, nullptr, nullptr);
    // G2: Y2 = CZ @ WBT^T + b_B
    gemm_ms<0><<<dim3(16, 32), 128, SMEM_TOTAL>>>(2048, 3072, 3072, CZ, WBT, b_B, Y2,
                                                  nullptr, nullptr, nullptr, nullptr);
    // G3: T = rna(w_prev @ AVT^T)   (w_prev raw: truncation noise attenuated in chain)
    gemm_ms<1><<<dim3(4, 32), 128, SMEM_TOTAL>>>(512, 2048, 2048, w_prev, AVT, nullptr, T,
                                                 nullptr, nullptr, nullptr, nullptr);
    // G4: out = Y1 * (tanh(A_diag)*0.9*w_prev + T @ A_U^T) + Y2
    gemm_ms<2><<<dim3(16, 32), 128, SMEM_TOTAL>>>(2048, 512, 512, T, A_U, nullptr, out,
                                                  Y1, Y2, w_prev, A_diag);
}

// round 10
// speedup vs baseline: 2.3296x; 1.5490x over previous
#include <cuda_runtime.h>
#include <cuda_fp16.h>
#include <cstdint>
#include <cstddef>

// ============================================================================
// WaveSubsystem, sm_103 legacy-tensor path (tcgen05 rejected by toolchain).
//   out = tanh(c@W_mod+b_mod) * (tanh(A_diag)*0.9*w + (w@A_V)@A_U^T) + [c|z]@W_B + b_B
// R8: fp16 m16n8k16 MMA (same 2^-11 roundoff as tf32, 2x tensor rate, half
// smem/DRAM bytes). 64x64 warp tile, BK=64, 3-stage cp.async ring.
// ============================================================================

#define BM 128
#define BN 128
#define BK 64
#define STAGE_BYTES 32768          // A 16KB + B 16KB (fp16)
#define NSTAGE 3
#define SMEM_TOTAL (STAGE_BYTES * NSTAGE)

// ---------------- scratch (__device__ globals; allocation-free rule) --------
__device__ __half g_CZ [4096ull*3072];   // fp16 [c|z]
__device__ __half g_Wh [4096ull*2048];   // fp16 w_prev
__device__ __half g_AUh[2048ull*512];    // fp16 A_U          [N,K]
__device__ __half g_WmT[2048ull*1024];   // fp16 W_mod^T      [N,K]
__device__ __half g_WBT[2048ull*3072];   // fp16 W_B^T        [N,K]
__device__ __half g_AVT[ 512ull*2048];   // fp16 A_V^T        [N,K]
__device__ __half g_T  [4096ull*512];    // fp16 w@A_V
__device__ float  g_Y1 [4096ull*2048];   // tanh(c@W_mod+b_mod)
__device__ float  g_Y2 [4096ull*2048];

// ---------------- helpers ---------------------------------------------------
__device__ __forceinline__ uint32_t smem_u32(const void* p) {
    uint32_t a;
    asm("{ .reg .u64 t; cvta.to.shared.u64 t, %1; cvt.u32.u64 %0, t; }"
        : "=r"(a) : "l"(p));
    return a;
}
#define CP_ASYNC16(dst, src) \
    asm volatile("cp.async.cg.shared.global [%0], [%1], 16;" :: "r"(dst), "l"(src))
#define CP_COMMIT()  asm volatile("cp.async.commit_group;" ::: "memory")
#define CP_WAIT(n)   asm volatile("cp.async.wait_group %0;" :: "n"(n) : "memory")

__device__ __forceinline__ void mma_f16(float c[4],
                                        const uint32_t a[4],
                                        const uint32_t b[2]) {
    asm volatile(
        "mma.sync.aligned.m16n8k16.row.col.f32.f16.f16.f32 "
        "{%0,%1,%2,%3}, {%4,%5,%6,%7}, {%8,%9}, {%0,%1,%2,%3};"
        : "+f"(c[0]), "+f"(c[1]), "+f"(c[2]), "+f"(c[3])
        : "r"(a[0]), "r"(a[1]), "r"(a[2]), "r"(a[3]),
          "r"(b[0]), "r"(b[1]));
}

// ---------------- pre-pass kernels ------------------------------------------
// fp32 -> fp16 copy with row restride (handles concat): 4 elems/thread
__global__ void half_cat(const float4* __restrict__ in, __half* __restrict__ out,
                         int n4, int os_h, int off_h, int total4) {
    int i = blockIdx.x * blockDim.x + threadIdx.x;
    if (i >= total4) return;
    int m = i / n4, k = i - m * n4;
    float4 v = in[i];
    __half2 h0 = __floats2half2_rn(v.x, v.y);
    __half2 h1 = __floats2half2_rn(v.z, v.w);
    uint2 r = make_uint2(*(uint32_t*)&h0, *(uint32_t*)&h1);
    *reinterpret_cast<uint2*>(&out[(size_t)m * os_h + off_h + 4 * k]) = r;
}

// transpose + fp16: in [R,C] fp32 -> out [C,R] fp16
__global__ void transpose_h(const float* __restrict__ in, __half* __restrict__ out,
                            int R, int C) {
    __shared__ float t[32][33];
    int x  = blockIdx.x * 32 + threadIdx.x;
    int y0 = blockIdx.y * 32;
    #pragma unroll
    for (int j = 0; j < 32; j += 8)
        t[threadIdx.y + j][threadIdx.x] = in[(size_t)(y0 + threadIdx.y + j) * C + x];
    __syncthreads();
    int ox  = y0 + threadIdx.x;
    int oy0 = blockIdx.x * 32;
    #pragma unroll
    for (int j = 0; j < 32; j += 8)
        out[(size_t)(oy0 + threadIdx.y + j) * R + ox] =
            __float2half_rn(t[threadIdx.x][threadIdx.y + j]);
}

// ---------------- unified GEMM: C[M,N] = A[M,K] @ B[N,K]^T (fp16 in, f32 acc)
// smem per stage: 128B rows (64 halves), 16B-granule xor swizzle
//   addr(row, j) = row*128 + ((j ^ (row&7))<<4)     j = 16B granule 0..7
// 4 warps (2x2), warp tile 64x64. EPI: 0=+bias 1=half-store 2=final-fused 3=tanh(+bias)
template <int EPI>
__global__ __launch_bounds__(128, 2)
void gemm_h(int N_total, int K, int lda,
            const __half* __restrict__ A, const __half* __restrict__ B,
            const float* __restrict__ bias, void* __restrict__ Cv,
            const float* __restrict__ Ey1, const float* __restrict__ Ey2,
            const float* __restrict__ Ew, const float* __restrict__ Ead)
{
    extern __shared__ __align__(128) char sm[];
    const uint32_t sb = smem_u32(sm);
    const int tid  = threadIdx.x;
    const int warp = tid >> 5, lane = tid & 31;
    const int wm = warp & 1, wn = warp >> 1;       // 2x2 warps, 64x64 tiles
    const int g  = lane >> 2, tg = lane & 3;
    const int m0 = blockIdx.y * BM, n0 = blockIdx.x * BN;

    // producer state (compact): thread covers rows r0+16i, fixed granule j
    const int r0 = tid >> 3, j = tid & 7;
    const __half* pA0 = A + (size_t)(m0 + r0) * lda + j * 8;
    const __half* pB0 = B + (size_t)(n0 + r0) * K + j * 8;
    const size_t aStep = (size_t)16 * lda;     // halves per i-step
    const size_t bStep = (size_t)16 * K;
    const uint32_t dA0 = r0 * 128 + ((j ^ (r0 & 7)) << 4);
    const uint32_t dB0 = 16384u + dA0;

    float acc[4][8][4];
    #pragma unroll
    for (int mi = 0; mi < 4; mi++)
        #pragma unroll
        for (int ni = 0; ni < 8; ni++)
            #pragma unroll
            for (int q = 0; q < 4; q++) acc[mi][ni][q] = 0.f;

    const int KT = K >> 6;                     // BK = 64
    auto produce = [&](int kt) {
        uint32_t base = sb + (uint32_t)(kt % NSTAGE) * STAGE_BYTES;
        int ko = kt << 6;                      // halves
        #pragma unroll
        for (int i = 0; i < 8; i++) CP_ASYNC16(base + dA0 + i * 2048, pA0 + i * aStep + ko);
        #pragma unroll
        for (int i = 0; i < 8; i++) CP_ASYNC16(base + dB0 + i * 2048, pB0 + i * bStep + ko);
        CP_COMMIT();
    };

    produce(0);
    produce(1);                                // all K >= 512 here
    #pragma unroll 1
    for (int kt = 0; kt < KT; kt++) {
        if (kt == KT - 1) { CP_WAIT(0); } else { CP_WAIT(1); }
        __syncthreads();
        if (kt + 2 < KT) produce(kt + 2);      // overwrites stage (kt-1)%3

        const char* sA = sm + (kt % NSTAGE) * STAGE_BYTES;
        const char* sB = sA + 16384;

        #pragma unroll
        for (int ks = 0; ks < 4; ks++) {       // 4 x k16
            uint32_t bf[8][2];
            #pragma unroll
            for (int ni = 0; ni < 8; ni++) {
                int n = wn * 64 + ni * 8 + g;
                uint32_t rowb = (uint32_t)n * 128 + 4 * tg;
                bf[ni][0] = *(const uint32_t*)(sB + rowb + (((2*ks)   ^ (n & 7)) << 4));
                bf[ni][1] = *(const uint32_t*)(sB + rowb + (((2*ks+1) ^ (n & 7)) << 4));
            }
            #pragma unroll
            for (int mi = 0; mi < 4; mi++) {
                int r = wm * 64 + mi * 16 + g;
                uint32_t sw0 = ((2*ks)   ^ (r & 7)) << 4;
                uint32_t sw1 = ((2*ks+1) ^ (r & 7)) << 4;
                uint32_t rowa = (uint32_t)r * 128 + 4 * tg;
                uint32_t af[4];
                af[0] = *(const uint32_t*)(sA + rowa + sw0);
                af[1] = *(const uint32_t*)(sA + rowa + 1024 + sw0);   // row r+8
                af[2] = *(const uint32_t*)(sA + rowa + sw1);
                af[3] = *(const uint32_t*)(sA + rowa + 1024 + sw1);
                #pragma unroll
                for (int ni = 0; ni < 8; ni++)
                    mma_f16(acc[mi][ni], af, bf[ni]);
            }
        }
    }

    // ---- epilogue ----
    #pragma unroll
    for (int mi = 0; mi < 4; mi++) {
        #pragma unroll
        for (int rr = 0; rr < 2; rr++) {
            int row = m0 + wm * 64 + mi * 16 + g + rr * 8;
            #pragma unroll
            for (int ni = 0; ni < 8; ni++) {
                int col = n0 + wn * 64 + ni * 8 + tg * 2;
                size_t idx = (size_t)row * N_total + col;
                float v0 = acc[mi][ni][rr * 2 + 0];
                float v1 = acc[mi][ni][rr * 2 + 1];
                if (EPI == 0) {
                    float* C = (float*)Cv;
                    v0 += bias[col]; v1 += bias[col + 1];
                    *reinterpret_cast<float2*>(&C[idx]) = make_float2(v0, v1);
                } else if (EPI == 3) {
                    float* C = (float*)Cv;
                    v0 = tanhf(v0 + bias[col]); v1 = tanhf(v1 + bias[col + 1]);
                    *reinterpret_cast<float2*>(&C[idx]) = make_float2(v0, v1);
                } else if (EPI == 1) {
                    __half* C = (__half*)Cv;
                    __half2 h = __floats2half2_rn(v0, v1);
                    *reinterpret_cast<__half2*>(&C[idx]) = h;
                } else {
                    float* C = (float*)Cv;
                    float2 y1 = *reinterpret_cast<const float2*>(&Ey1[idx]);
                    float2 y2 = *reinterpret_cast<const float2*>(&Ey2[idx]);
                    float2 w  = *reinterpret_cast<const float2*>(&Ew[idx]);
                    float ad0 = tanhf(Ead[col])     * 0.9f;
                    float ad1 = tanhf(Ead[col + 1]) * 0.9f;
                    float o0 = y1.x * (ad0 * w.x + v0) + y2.x;
                    float o1 = y1.y * (ad1 * w.y + v1) + y2.y;
                    *reinterpret_cast<float2*>(&C[idx]) = make_float2(o0, o1);
                }
            }
        }
    }
}

// ---------------- host ------------------------------------------------------
extern "C" void kernel_launch(void* const* d_in, const int* in_sizes, int n_in,
                              void* d_out, int out_size)
{
    const float* w_prev = (const float*)d_in[0];   // [4096,2048]
    const float* z_t    = (const float*)d_in[1];   // [4096,2048]
    const float* c_t    = (const float*)d_in[2];   // [4096,1024]
    const float* A_diag = (const float*)d_in[3];   // [2048]
    const float* A_U    = (const float*)d_in[4];   // [2048,512]  already [N,K]
    const float* A_V    = (const float*)d_in[5];   // [2048,512]
    const float* W_mod  = (const float*)d_in[6];   // [1024,2048]
    const float* b_mod  = (const float*)d_in[7];
    const float* W_B    = (const float*)d_in[8];   // [3072,2048]
    const float* b_B    = (const float*)d_in[9];
    float* out = (float*)d_out;                    // [4096,2048]
    (void)in_sizes; (void)n_in; (void)out_size;

    __half *CZ, *Wh, *AUh, *WmT, *WBT, *AVT, *T;
    float *Y1, *Y2;
    cudaGetSymbolAddress((void**)&CZ,  g_CZ);
    cudaGetSymbolAddress((void**)&Wh,  g_Wh);
    cudaGetSymbolAddress((void**)&AUh, g_AUh);
    cudaGetSymbolAddress((void**)&WmT, g_WmT);
    cudaGetSymbolAddress((void**)&WBT, g_WBT);
    cudaGetSymbolAddress((void**)&AVT, g_AVT);
    cudaGetSymbolAddress((void**)&T,   g_T);
    cudaGetSymbolAddress((void**)&Y1,  g_Y1);
    cudaGetSymbolAddress((void**)&Y2,  g_Y2);

    cudaFuncSetAttribute(gemm_h<0>, cudaFuncAttributeMaxDynamicSharedMemorySize, SMEM_TOTAL);
    cudaFuncSetAttribute(gemm_h<1>, cudaFuncAttributeMaxDynamicSharedMemorySize, SMEM_TOTAL);
    cudaFuncSetAttribute(gemm_h<2>, cudaFuncAttributeMaxDynamicSharedMemorySize, SMEM_TOTAL);
    cudaFuncSetAttribute(gemm_h<3>, cudaFuncAttributeMaxDynamicSharedMemorySize, SMEM_TOTAL);

    // pre-passes: fp32 -> fp16 (RNE); weights also transposed to [N,K]
    half_cat<<<4096, 256>>>((const float4*)c_t,    CZ,  256, 3072, 0,    1048576);
    half_cat<<<8192, 256>>>((const float4*)z_t,    CZ,  512, 3072, 1024, 2097152);
    half_cat<<<8192, 256>>>((const float4*)w_prev, Wh,  512, 2048, 0,    2097152);
    half_cat<<<1024, 256>>>((const float4*)A_U,    AUh, 128,  512, 0,     262144);
    transpose_h<<<dim3(64, 32), dim3(32, 8)>>>(W_mod, WmT, 1024, 2048);
    transpose_h<<<dim3(64, 96), dim3(32, 8)>>>(W_B,   WBT, 3072, 2048);
    transpose_h<<<dim3(16, 64), dim3(32, 8)>>>(A_V,   AVT, 2048, 512);

    // G1: Y1 = tanh(CZ[:, :1024] @ WmT^T + b_mod)
    gemm_h<3><<<dim3(16, 32), 128, SMEM_TOTAL>>>(2048, 1024, 3072, CZ, WmT, b_mod, Y1,
                                                 nullptr, nullptr, nullptr, nullptr);
    // G2: Y2 = CZ @ WBT^T + b_B
    gemm_h<0><<<dim3(16, 32), 128, SMEM_TOTAL>>>(2048, 3072, 3072, CZ, WBT, b_B, Y2,
                                                 nullptr, nullptr, nullptr, nullptr);
    // G3: T = fp16(Wh @ AVT^T)
    gemm_h<1><<<dim3(4, 32), 128, SMEM_TOTAL>>>(512, 2048, 2048, Wh, AVT, nullptr, T,
                                                nullptr, nullptr, nullptr, nullptr);
    // G4: out = Y1 * (tanh(A_diag)*0.9*w_prev + T @ A_U^T) + Y2
    gemm_h<2><<<dim3(16, 32), 128, SMEM_TOTAL>>>(2048, 512, 512, T, AUh, nullptr, out,
                                                 Y1, Y2, w_prev, A_diag);
}

// round 13
// speedup vs baseline: 2.5401x; 1.0904x over previous
#include <cuda_runtime.h>
#include <cuda_fp16.h>
#include <cstdint>
#include <cstddef>

// ============================================================================
// WaveSubsystem, sm_103 legacy-tensor path.
//   out = tanh(c@W_mod+b_mod) * (tanh(A_diag)*0.9*w + (w@A_V)@A_U^T) + [c|z]@W_B + b_B
// R12 = R10 with the B-operand ldmatrix fixed: B is [N,K] K-major, so its
// fragment uses NON-trans ldmatrix (same orientation as A). R11's `.trans`
// fed a transposed B tile to every MMA -> rel_err 1.32.
// ============================================================================

#define BM 128
#define BN 128
#define STAGE_BYTES 32768          // A 16KB + B 16KB (fp16, BK=64)
#define NSTAGE 3
#define SMEM_TOTAL (STAGE_BYTES * NSTAGE)

// ---------------- scratch (__device__ globals; allocation-free rule) --------
__device__ __half g_CZ [4096ull*3072];   // fp16 [c|z]
__device__ __half g_Wh [4096ull*2048];   // fp16 w_prev
__device__ __half g_AUh[2048ull*512];    // fp16 A_U          [N,K]
__device__ __half g_WmT[2048ull*1024];   // fp16 W_mod^T      [N,K]
__device__ __half g_WBT[2048ull*3072];   // fp16 W_B^T        [N,K]
__device__ __half g_AVT[ 512ull*2048];   // fp16 A_V^T        [N,K]
__device__ __half g_T  [4096ull*512];    // fp16 w@A_V
__device__ float  g_Y1 [4096ull*2048];   // tanh(c@W_mod+b_mod)
__device__ float  g_Y2 [4096ull*2048];

// ---------------- helpers ---------------------------------------------------
__device__ __forceinline__ uint32_t smem_u32(const void* p) {
    uint32_t a;
    asm("{ .reg .u64 t; cvta.to.shared.u64 t, %1; cvt.u32.u64 %0, t; }"
        : "=r"(a) : "l"(p));
    return a;
}
#define CP_ASYNC16(dst, src) \
    asm volatile("cp.async.cg.shared.global [%0], [%1], 16;" :: "r"(dst), "l"(src))
#define CP_COMMIT()  asm volatile("cp.async.commit_group;" ::: "memory")
#define CP_WAIT(n)   asm volatile("cp.async.wait_group %0;" :: "n"(n) : "memory")

#define LDSM_X4(r0, r1, r2, r3, addr) \
    asm volatile("ldmatrix.sync.aligned.m8n8.x4.shared.b16 {%0,%1,%2,%3}, [%4];" \
        : "=r"(r0), "=r"(r1), "=r"(r2), "=r"(r3) : "r"(addr))

__device__ __forceinline__ void mma_f16(float c[4],
                                        const uint32_t a[4],
                                        const uint32_t b[2]) {
    asm volatile(
        "mma.sync.aligned.m16n8k16.row.col.f32.f16.f16.f32 "
        "{%0,%1,%2,%3}, {%4,%5,%6,%7}, {%8,%9}, {%0,%1,%2,%3};"
        : "+f"(c[0]), "+f"(c[1]), "+f"(c[2]), "+f"(c[3])
        : "r"(a[0]), "r"(a[1]), "r"(a[2]), "r"(a[3]),
          "r"(b[0]), "r"(b[1]));
}

// ---------------- pre-pass 1: all fp32->fp16 copies (with concat restride) --
__global__ void conv_all(const float4* __restrict__ c, const float4* __restrict__ z,
                         const float4* __restrict__ w, const float4* __restrict__ au,
                         __half* __restrict__ CZ, __half* __restrict__ Wh,
                         __half* __restrict__ AUh) {
    int i = blockIdx.x * blockDim.x + threadIdx.x;
    const float4* in; __half* out; int n4, os, off;
    if (i < 1048576)      { in = c;  out = CZ;  n4 = 256; os = 3072; off = 0;    }
    else if (i < 3145728) { i -= 1048576; in = z;  out = CZ;  n4 = 512; os = 3072; off = 1024; }
    else if (i < 5242880) { i -= 3145728; in = w;  out = Wh;  n4 = 512; os = 2048; off = 0;    }
    else                  { i -= 5242880; if (i >= 262144) return;
                            in = au; out = AUh; n4 = 128; os = 512;  off = 0;    }
    int m = i / n4, k = i - m * n4;
    float4 v = in[i];
    __half2 h0 = __floats2half2_rn(v.x, v.y);
    __half2 h1 = __floats2half2_rn(v.z, v.w);
    uint2 r = make_uint2(*(uint32_t*)&h0, *(uint32_t*)&h1);
    *reinterpret_cast<uint2*>(&out[(size_t)m * os + off + 4 * k]) = r;
}

// ---------------- pre-pass 2: three transposes (fp32 [R,C] -> fp16 [C,R]) ---
__global__ void transpose3(const float* __restrict__ wb, const float* __restrict__ wm,
                           const float* __restrict__ av, __half* __restrict__ WBT,
                           __half* __restrict__ WmT, __half* __restrict__ AVT) {
    const float* in; __half* out; int R, C, gx, gy;
    if (blockIdx.z == 0)      { in = wb; out = WBT; R = 3072; C = 2048; gx = 64; gy = 96; }
    else if (blockIdx.z == 1) { in = wm; out = WmT; R = 1024; C = 2048; gx = 64; gy = 32; }
    else                      { in = av; out = AVT; R = 2048; C = 512;  gx = 16; gy = 64; }
    if ((int)blockIdx.x >= gx || (int)blockIdx.y >= gy) return;
    __shared__ float t[32][33];
    int x  = blockIdx.x * 32 + threadIdx.x;
    int y0 = blockIdx.y * 32;
    #pragma unroll
    for (int j = 0; j < 32; j += 8)
        t[threadIdx.y + j][threadIdx.x] = in[(size_t)(y0 + threadIdx.y + j) * C + x];
    __syncthreads();
    int ox  = y0 + threadIdx.x;
    int oy0 = blockIdx.x * 32;
    #pragma unroll
    for (int j = 0; j < 32; j += 8)
        out[(size_t)(oy0 + threadIdx.y + j) * R + ox] =
            __float2half_rn(t[threadIdx.x][threadIdx.y + j]);
}

// ---------------- unified GEMM: C[M,N] = A[M,K] @ B[N,K]^T (fp16, f32 acc) --
// smem per stage: 128B rows (64 halves), 16B-granule xor swizzle
//   addr(row, g) = row*128 + ((g ^ (row&7))<<4),  granule g = 0..7
// 4 warps (2x2), 64x64 warp tiles. epi: 0=+bias 1=half 2=final-fused 3=tanh(+bias)
struct GCfg {
    const __half* A; const __half* B;
    const float* bias; void* C;
    int K, N, lda, epi, gx;
};
struct GCfg3 { GCfg g0, g1, g2; };

__global__ __launch_bounds__(128, 2)
void gemm_multi(GCfg3 cfgs,
                const float* __restrict__ Ey1, const float* __restrict__ Ey2,
                const float* __restrict__ Ew, const float* __restrict__ Ead)
{
    GCfg cf = cfgs.g0;
    if (blockIdx.z == 1) cf = cfgs.g1;
    else if (blockIdx.z == 2) cf = cfgs.g2;
    if ((int)blockIdx.x >= cf.gx) return;

    extern __shared__ __align__(128) char sm[];
    const uint32_t sb = smem_u32(sm);
    const int tid  = threadIdx.x;
    const int warp = tid >> 5, lane = tid & 31;
    const int wm = warp & 1, wn = warp >> 1;       // 2x2 warps, 64x64 tiles
    const int g  = lane >> 2, tg = lane & 3;
    const int m0 = blockIdx.y * BM, n0 = blockIdx.x * BN;
    const int K = cf.K, lda = cf.lda, N_total = cf.N;

    // ---- producer constants ----
    const int r0 = tid >> 3, jg = tid & 7;
    const __half* pA0 = cf.A + (size_t)(m0 + r0) * lda + jg * 8;
    const __half* pB0 = cf.B + (size_t)(n0 + r0) * K + jg * 8;
    const size_t aStep = (size_t)16 * lda;
    const size_t bStep = (size_t)16 * K;
    const uint32_t dA0 = r0 * 128 + ((jg ^ (r0 & 7)) << 4);
    const uint32_t dB0 = 16384u + dA0;

    // ---- ldmatrix per-lane address constants ----
    // x4 matrices are addressed by lane groups [0-7],[8-15],[16-23],[24-31];
    // regs 0..3 come from those groups in order. Both A and B are K-major, so
    // both use NON-trans ldmatrix (pairs contiguous along K).
    const int mA = lane >> 3, iA = lane & 7;
    // A: matrices = (rows+0-7,gran+0),(rows+8-15,gran+0),(rows+0-7,gran+1),(rows+8-15,gran+1)
    uint32_t aBase[4], aXor[4];
    #pragma unroll
    for (int mi = 0; mi < 4; mi++) {
        int row = wm * 64 + mi * 16 + (mA & 1) * 8 + iA;
        aBase[mi] = (uint32_t)row * 128;
        aXor[mi]  = (uint32_t)(row & 7);
    }
    const uint32_t aHi = (uint32_t)(mA >> 1);
    // B: matrices = (rows+0-7,gran+0),(rows+0-7,gran+1),(rows+8-15,gran+0),(rows+8-15,gran+1)
    uint32_t bBase[4], bXor[4];
    #pragma unroll
    for (int p = 0; p < 4; p++) {
        int row = wn * 64 + p * 16 + ((mA >> 1) << 3) + iA;
        bBase[p] = 16384u + (uint32_t)row * 128;
        bXor[p]  = (uint32_t)(row & 7);
    }
    const uint32_t bHi = (uint32_t)(mA & 1);

    float acc[4][8][4];
    #pragma unroll
    for (int mi = 0; mi < 4; mi++)
        #pragma unroll
        for (int ni = 0; ni < 8; ni++)
            #pragma unroll
            for (int q = 0; q < 4; q++) acc[mi][ni][q] = 0.f;

    const int KT = K >> 6;                     // BK = 64
    auto produce = [&](int kt) {
        uint32_t base = sb + (uint32_t)(kt % NSTAGE) * STAGE_BYTES;
        int ko = kt << 6;
        #pragma unroll
        for (int i = 0; i < 8; i++) CP_ASYNC16(base + dA0 + i * 2048, pA0 + i * aStep + ko);
        #pragma unroll
        for (int i = 0; i < 8; i++) CP_ASYNC16(base + dB0 + i * 2048, pB0 + i * bStep + ko);
        CP_COMMIT();
    };

    produce(0);
    produce(1);
    #pragma unroll 1
    for (int kt = 0; kt < KT; kt++) {
        if (kt == KT - 1) { CP_WAIT(0); } else { CP_WAIT(1); }
        __syncthreads();
        if (kt + 2 < KT) produce(kt + 2);

        const uint32_t sBase = sb + (uint32_t)(kt % NSTAGE) * STAGE_BYTES;

        #pragma unroll
        for (int ks = 0; ks < 4; ks++) {
            uint32_t bf[8][2];
            #pragma unroll
            for (int p = 0; p < 4; p++) {
                uint32_t addr = sBase + bBase[p] + (((2u*ks + bHi) ^ bXor[p]) << 4);
                LDSM_X4(bf[2*p][0], bf[2*p][1], bf[2*p+1][0], bf[2*p+1][1], addr);
            }
            #pragma unroll
            for (int mi = 0; mi < 4; mi++) {
                uint32_t af[4];
                uint32_t addr = sBase + aBase[mi] + (((2u*ks + aHi) ^ aXor[mi]) << 4);
                LDSM_X4(af[0], af[1], af[2], af[3], addr);
                #pragma unroll
                for (int ni = 0; ni < 8; ni++)
                    mma_f16(acc[mi][ni], af, bf[ni]);
            }
        }
    }

    // ---- epilogue ----
    const int epi = cf.epi;
    #pragma unroll
    for (int mi = 0; mi < 4; mi++) {
        #pragma unroll
        for (int rr = 0; rr < 2; rr++) {
            int row = m0 + wm * 64 + mi * 16 + g + rr * 8;
            #pragma unroll
            for (int ni = 0; ni < 8; ni++) {
                int col = n0 + wn * 64 + ni * 8 + tg * 2;
                size_t idx = (size_t)row * N_total + col;
                float v0 = acc[mi][ni][rr * 2 + 0];
                float v1 = acc[mi][ni][rr * 2 + 1];
                if (epi == 0) {
                    float* C = (float*)cf.C;
                    v0 += cf.bias[col]; v1 += cf.bias[col + 1];
                    *reinterpret_cast<float2*>(&C[idx]) = make_float2(v0, v1);
                } else if (epi == 3) {
                    float* C = (float*)cf.C;
                    v0 = tanhf(v0 + cf.bias[col]); v1 = tanhf(v1 + cf.bias[col + 1]);
                    *reinterpret_cast<float2*>(&C[idx]) = make_float2(v0, v1);
                } else if (epi == 1) {
                    __half* C = (__half*)cf.C;
                    __half2 h = __floats2half2_rn(v0, v1);
                    *reinterpret_cast<__half2*>(&C[idx]) = h;
                } else {
                    float* C = (float*)cf.C;
                    float2 y1 = *reinterpret_cast<const float2*>(&Ey1[idx]);
                    float2 y2 = *reinterpret_cast<const float2*>(&Ey2[idx]);
                    float2 w  = *reinterpret_cast<const float2*>(&Ew[idx]);
                    float ad0 = tanhf(Ead[col])     * 0.9f;
                    float ad1 = tanhf(Ead[col + 1]) * 0.9f;
                    float o0 = y1.x * (ad0 * w.x + v0) + y2.x;
                    float o1 = y1.y * (ad1 * w.y + v1) + y2.y;
                    *reinterpret_cast<float2*>(&C[idx]) = make_float2(o0, o1);
                }
            }
        }
    }
}

// ---------------- host ------------------------------------------------------
extern "C" void kernel_launch(void* const* d_in, const int* in_sizes, int n_in,
                              void* d_out, int out_size)
{
    const float* w_prev = (const float*)d_in[0];   // [4096,2048]
    const float* z_t    = (const float*)d_in[1];   // [4096,2048]
    const float* c_t    = (const float*)d_in[2];   // [4096,1024]
    const float* A_diag = (const float*)d_in[3];   // [2048]
    const float* A_U    = (const float*)d_in[4];   // [2048,512]
    const float* A_V    = (const float*)d_in[5];   // [2048,512]
    const float* W_mod  = (const float*)d_in[6];   // [1024,2048]
    const float* b_mod  = (const float*)d_in[7];
    const float* W_B    = (const float*)d_in[8];   // [3072,2048]
    const float* b_B    = (const float*)d_in[9];
    float* out = (float*)d_out;                    // [4096,2048]
    (void)in_sizes; (void)n_in; (void)out_size;

    __half *CZ, *Wh, *AUh, *WmT, *WBT, *AVT, *T;
    float *Y1, *Y2;
    cudaGetSymbolAddress((void**)&CZ,  g_CZ);
    cudaGetSymbolAddress((void**)&Wh,  g_Wh);
    cudaGetSymbolAddress((void**)&AUh, g_AUh);
    cudaGetSymbolAddress((void**)&WmT, g_WmT);
    cudaGetSymbolAddress((void**)&WBT, g_WBT);
    cudaGetSymbolAddress((void**)&AVT, g_AVT);
    cudaGetSymbolAddress((void**)&T,   g_T);
    cudaGetSymbolAddress((void**)&Y1,  g_Y1);
    cudaGetSymbolAddress((void**)&Y2,  g_Y2);

    cudaFuncSetAttribute(gemm_multi, cudaFuncAttributeMaxDynamicSharedMemorySize, SMEM_TOTAL);

    // pre-pass 1: all fp32->fp16 copies (c|z concat, w_prev, A_U)
    conv_all<<<21504, 256>>>((const float4*)c_t, (const float4*)z_t,
                             (const float4*)w_prev, (const float4*)A_U,
                             CZ, Wh, AUh);
    // pre-pass 2: three weight transposes
    transpose3<<<dim3(64, 96, 3), dim3(32, 8)>>>(W_B, W_mod, A_V, WBT, WmT, AVT);

    // merged G2 (z=0, longest K first) + G1 (z=1) + G3 (z=2)
    GCfg3 cf;
    cf.g0 = { CZ, WBT, b_B,   (void*)Y2, 3072, 2048, 3072, 0, 16 };  // G2
    cf.g1 = { CZ, WmT, b_mod, (void*)Y1, 1024, 2048, 3072, 3, 16 };  // G1
    cf.g2 = { Wh, AVT, nullptr, (void*)T, 2048, 512, 2048, 1, 4 };   // G3
    gemm_multi<<<dim3(16, 32, 3), 128, SMEM_TOTAL>>>(cf, nullptr, nullptr, nullptr, nullptr);

    // G4: out = Y1 * (tanh(A_diag)*0.9*w_prev + T @ A_U^T) + Y2
    GCfg3 cf4;
    cf4.g0 = { T, AUh, nullptr, (void*)out, 512, 2048, 512, 2, 16 }; // G4
    cf4.g1 = cf4.g0; cf4.g2 = cf4.g0;
    gemm_multi<<<dim3(16, 32, 1), 128, SMEM_TOTAL>>>(cf4, Y1, Y2, w_prev, A_diag);
}

// round 14
// speedup vs baseline: 2.8678x; 1.1290x over previous
#include <cuda_runtime.h>
#include <cuda_fp16.h>
#include <cstdint>
#include <cstddef>

// ============================================================================
// WaveSubsystem, sm_103 legacy-tensor path.
//   out = tanh(c@W_mod+b_mod) * (tanh(A_diag)*0.9*w + (w@A_V)@A_U^T) + [c|z]@W_B + b_B
// R13: Y1/Y2 stored fp16 (halves G4 epilogue + merged-store traffic);
// dedicated 256-thread G4 kernel (2x occupancy for the latency-bound epilogue).
// Mainloop/ldmatrix/swizzle identical to the verified R12.
// ============================================================================

#define BM 128
#define BN 128
#define STAGE_BYTES 32768          // A 16KB + B 16KB (fp16, BK=64)
#define NSTAGE 3
#define SMEM_TOTAL (STAGE_BYTES * NSTAGE)

// ---------------- scratch (__device__ globals; allocation-free rule) --------
__device__ __half g_CZ [4096ull*3072];   // fp16 [c|z]
__device__ __half g_Wh [4096ull*2048];   // fp16 w_prev
__device__ __half g_AUh[2048ull*512];    // fp16 A_U          [N,K]
__device__ __half g_WmT[2048ull*1024];   // fp16 W_mod^T      [N,K]
__device__ __half g_WBT[2048ull*3072];   // fp16 W_B^T        [N,K]
__device__ __half g_AVT[ 512ull*2048];   // fp16 A_V^T        [N,K]
__device__ __half g_T  [4096ull*512];    // fp16 w@A_V
__device__ __half g_Y1 [4096ull*2048];   // fp16 tanh(c@W_mod+b_mod)
__device__ __half g_Y2 [4096ull*2048];   // fp16 [c|z]@W_B + b_B

// ---------------- helpers ---------------------------------------------------
__device__ __forceinline__ uint32_t smem_u32(const void* p) {
    uint32_t a;
    asm("{ .reg .u64 t; cvta.to.shared.u64 t, %1; cvt.u32.u64 %0, t; }"
        : "=r"(a) : "l"(p));
    return a;
}
#define CP_ASYNC16(dst, src) \
    asm volatile("cp.async.cg.shared.global [%0], [%1], 16;" :: "r"(dst), "l"(src))
#define CP_COMMIT()  asm volatile("cp.async.commit_group;" ::: "memory")
#define CP_WAIT(n)   asm volatile("cp.async.wait_group %0;" :: "n"(n) : "memory")

#define LDSM_X4(r0, r1, r2, r3, addr) \
    asm volatile("ldmatrix.sync.aligned.m8n8.x4.shared.b16 {%0,%1,%2,%3}, [%4];" \
        : "=r"(r0), "=r"(r1), "=r"(r2), "=r"(r3) : "r"(addr))

__device__ __forceinline__ void mma_f16(float c[4],
                                        const uint32_t a[4],
                                        const uint32_t b[2]) {
    asm volatile(
        "mma.sync.aligned.m16n8k16.row.col.f32.f16.f16.f32 "
        "{%0,%1,%2,%3}, {%4,%5,%6,%7}, {%8,%9}, {%0,%1,%2,%3};"
        : "+f"(c[0]), "+f"(c[1]), "+f"(c[2]), "+f"(c[3])
        : "r"(a[0]), "r"(a[1]), "r"(a[2]), "r"(a[3]),
          "r"(b[0]), "r"(b[1]));
}

// ---------------- pre-pass 1: all fp32->fp16 copies (with concat restride) --
__global__ void conv_all(const float4* __restrict__ c, const float4* __restrict__ z,
                         const float4* __restrict__ w, const float4* __restrict__ au,
                         __half* __restrict__ CZ, __half* __restrict__ Wh,
                         __half* __restrict__ AUh) {
    int i = blockIdx.x * blockDim.x + threadIdx.x;
    const float4* in; __half* out; int n4, os, off;
    if (i < 1048576)      { in = c;  out = CZ;  n4 = 256; os = 3072; off = 0;    }
    else if (i < 3145728) { i -= 1048576; in = z;  out = CZ;  n4 = 512; os = 3072; off = 1024; }
    else if (i < 5242880) { i -= 3145728; in = w;  out = Wh;  n4 = 512; os = 2048; off = 0;    }
    else                  { i -= 5242880; if (i >= 262144) return;
                            in = au; out = AUh; n4 = 128; os = 512;  off = 0;    }
    int m = i / n4, k = i - m * n4;
    float4 v = in[i];
    __half2 h0 = __floats2half2_rn(v.x, v.y);
    __half2 h1 = __floats2half2_rn(v.z, v.w);
    uint2 r = make_uint2(*(uint32_t*)&h0, *(uint32_t*)&h1);
    *reinterpret_cast<uint2*>(&out[(size_t)m * os + off + 4 * k]) = r;
}

// ---------------- pre-pass 2: three transposes (fp32 [R,C] -> fp16 [C,R]) ---
__global__ void transpose3(const float* __restrict__ wb, const float* __restrict__ wm,
                           const float* __restrict__ av, __half* __restrict__ WBT,
                           __half* __restrict__ WmT, __half* __restrict__ AVT) {
    const float* in; __half* out; int R, C, gx, gy;
    if (blockIdx.z == 0)      { in = wb; out = WBT; R = 3072; C = 2048; gx = 64; gy = 96; }
    else if (blockIdx.z == 1) { in = wm; out = WmT; R = 1024; C = 2048; gx = 64; gy = 32; }
    else                      { in = av; out = AVT; R = 2048; C = 512;  gx = 16; gy = 64; }
    if ((int)blockIdx.x >= gx || (int)blockIdx.y >= gy) return;
    __shared__ float t[32][33];
    int x  = blockIdx.x * 32 + threadIdx.x;
    int y0 = blockIdx.y * 32;
    #pragma unroll
    for (int j = 0; j < 32; j += 8)
        t[threadIdx.y + j][threadIdx.x] = in[(size_t)(y0 + threadIdx.y + j) * C + x];
    __syncthreads();
    int ox  = y0 + threadIdx.x;
    int oy0 = blockIdx.x * 32;
    #pragma unroll
    for (int j = 0; j < 32; j += 8)
        out[(size_t)(oy0 + threadIdx.y + j) * R + ox] =
            __float2half_rn(t[threadIdx.x][threadIdx.y + j]);
}

// ---------------- merged GEMM G1/G2/G3: C = A @ B^T, fp16 stores ------------
// smem per stage: 128B rows (64 halves), 16B-granule xor swizzle. 4 warps 2x2.
// epi: 1 = plain->fp16   3 = tanh(v+bias)->fp16   4 = (v+bias)->fp16
struct GCfg {
    const __half* A; const __half* B;
    const float* bias; __half* C;
    int K, N, lda, epi, gx;
};
struct GCfg3 { GCfg g0, g1, g2; };

__global__ __launch_bounds__(128, 2)
void gemm_multi(GCfg3 cfgs)
{
    GCfg cf = cfgs.g0;
    if (blockIdx.z == 1) cf = cfgs.g1;
    else if (blockIdx.z == 2) cf = cfgs.g2;
    if ((int)blockIdx.x >= cf.gx) return;

    extern __shared__ __align__(128) char sm[];
    const uint32_t sb = smem_u32(sm);
    const int tid  = threadIdx.x;
    const int warp = tid >> 5, lane = tid & 31;
    const int wm = warp & 1, wn = warp >> 1;       // 2x2 warps, 64x64 tiles
    const int g  = lane >> 2, tg = lane & 3;
    const int m0 = blockIdx.y * BM, n0 = blockIdx.x * BN;
    const int K = cf.K, lda = cf.lda, N_total = cf.N;

    const int r0 = tid >> 3, jg = tid & 7;
    const __half* pA0 = cf.A + (size_t)(m0 + r0) * lda + jg * 8;
    const __half* pB0 = cf.B + (size_t)(n0 + r0) * K + jg * 8;
    const size_t aStep = (size_t)16 * lda;
    const size_t bStep = (size_t)16 * K;
    const uint32_t dA0 = r0 * 128 + ((jg ^ (r0 & 7)) << 4);
    const uint32_t dB0 = 16384u + dA0;

    const int mA = lane >> 3, iA = lane & 7;
    uint32_t aBase[4], aXor[4];
    #pragma unroll
    for (int mi = 0; mi < 4; mi++) {
        int row = wm * 64 + mi * 16 + (mA & 1) * 8 + iA;
        aBase[mi] = (uint32_t)row * 128;
        aXor[mi]  = (uint32_t)(row & 7);
    }
    const uint32_t aHi = (uint32_t)(mA >> 1);
    uint32_t bBase[4], bXor[4];
    #pragma unroll
    for (int p = 0; p < 4; p++) {
        int row = wn * 64 + p * 16 + ((mA >> 1) << 3) + iA;
        bBase[p] = 16384u + (uint32_t)row * 128;
        bXor[p]  = (uint32_t)(row & 7);
    }
    const uint32_t bHi = (uint32_t)(mA & 1);

    float acc[4][8][4];
    #pragma unroll
    for (int mi = 0; mi < 4; mi++)
        #pragma unroll
        for (int ni = 0; ni < 8; ni++)
            #pragma unroll
            for (int q = 0; q < 4; q++) acc[mi][ni][q] = 0.f;

    const int KT = K >> 6;                     // BK = 64
    auto produce = [&](int kt) {
        uint32_t base = sb + (uint32_t)(kt % NSTAGE) * STAGE_BYTES;
        int ko = kt << 6;
        #pragma unroll
        for (int i = 0; i < 8; i++) CP_ASYNC16(base + dA0 + i * 2048, pA0 + i * aStep + ko);
        #pragma unroll
        for (int i = 0; i < 8; i++) CP_ASYNC16(base + dB0 + i * 2048, pB0 + i * bStep + ko);
        CP_COMMIT();
    };

    produce(0);
    produce(1);
    #pragma unroll 1
    for (int kt = 0; kt < KT; kt++) {
        if (kt == KT - 1) { CP_WAIT(0); } else { CP_WAIT(1); }
        __syncthreads();
        if (kt + 2 < KT) produce(kt + 2);

        const uint32_t sBase = sb + (uint32_t)(kt % NSTAGE) * STAGE_BYTES;

        #pragma unroll
        for (int ks = 0; ks < 4; ks++) {
            uint32_t bf[8][2];
            #pragma unroll
            for (int p = 0; p < 4; p++) {
                uint32_t addr = sBase + bBase[p] + (((2u*ks + bHi) ^ bXor[p]) << 4);
                LDSM_X4(bf[2*p][0], bf[2*p][1], bf[2*p+1][0], bf[2*p+1][1], addr);
            }
            #pragma unroll
            for (int mi = 0; mi < 4; mi++) {
                uint32_t af[4];
                uint32_t addr = sBase + aBase[mi] + (((2u*ks + aHi) ^ aXor[mi]) << 4);
                LDSM_X4(af[0], af[1], af[2], af[3], addr);
                #pragma unroll
                for (int ni = 0; ni < 8; ni++)
                    mma_f16(acc[mi][ni], af, bf[ni]);
            }
        }
    }

    // ---- epilogue: fp16 stores ----
    const int epi = cf.epi;
    #pragma unroll
    for (int mi = 0; mi < 4; mi++) {
        #pragma unroll
        for (int rr = 0; rr < 2; rr++) {
            int row = m0 + wm * 64 + mi * 16 + g + rr * 8;
            #pragma unroll
            for (int ni = 0; ni < 8; ni++) {
                int col = n0 + wn * 64 + ni * 8 + tg * 2;
                size_t idx = (size_t)row * N_total + col;
                float v0 = acc[mi][ni][rr * 2 + 0];
                float v1 = acc[mi][ni][rr * 2 + 1];
                if (epi == 3) {
                    v0 = tanhf(v0 + cf.bias[col]); v1 = tanhf(v1 + cf.bias[col + 1]);
                } else if (epi == 4) {
                    v0 += cf.bias[col]; v1 += cf.bias[col + 1];
                }
                __half2 h = __floats2half2_rn(v0, v1);
                *reinterpret_cast<__half2*>(&cf.C[idx]) = h;
            }
        }
    }
}

// ---------------- G4: out = Y1 * (ad*w + T@AU^T) + Y2 (all fp16 streams) ----
// 256 threads, 8 warps (2x4), warp tile 64x32. CTA 128x128, K=512.
__global__ __launch_bounds__(256, 2)
void gemm_g4(const __half* __restrict__ A,   // T  [4096,512]
             const __half* __restrict__ B,   // AUh [2048,512]
             const __half* __restrict__ Y1h,
             const __half* __restrict__ Y2h,
             const __half* __restrict__ Wh,
             const float* __restrict__ Ad,
             float* __restrict__ out)
{
    extern __shared__ __align__(128) char sm[];
    const uint32_t sb = smem_u32(sm);
    const int tid  = threadIdx.x;
    const int warp = tid >> 5, lane = tid & 31;
    const int wm = warp & 1, wn = warp >> 1;       // 2x4 warps, 64x32 tiles
    const int g  = lane >> 2, tg = lane & 3;
    const int m0 = blockIdx.y * BM, n0 = blockIdx.x * BN;
    const int K = 512, N_total = 2048;

    // producer: 256 threads, 4 A + 4 B granules each (rows step 32)
    const int r0 = tid >> 3, jg = tid & 7;
    const __half* pA0 = A + (size_t)(m0 + r0) * K + jg * 8;
    const __half* pB0 = B + (size_t)(n0 + r0) * K + jg * 8;
    const size_t rStep = (size_t)32 * K;
    const uint32_t dA0 = r0 * 128 + ((jg ^ (r0 & 7)) << 4);
    const uint32_t dB0 = 16384u + dA0;

    const int mA = lane >> 3, iA = lane & 7;
    uint32_t aBase[4], aXor[4];
    #pragma unroll
    for (int mi = 0; mi < 4; mi++) {
        int row = wm * 64 + mi * 16 + (mA & 1) * 8 + iA;
        aBase[mi] = (uint32_t)row * 128;
        aXor[mi]  = (uint32_t)(row & 7);
    }
    const uint32_t aHi = (uint32_t)(mA >> 1);
    uint32_t bBase[2], bXor[2];
    #pragma unroll
    for (int p = 0; p < 2; p++) {
        int row = wn * 32 + p * 16 + ((mA >> 1) << 3) + iA;
        bBase[p] = 16384u + (uint32_t)row * 128;
        bXor[p]  = (uint32_t)(row & 7);
    }
    const uint32_t bHi = (uint32_t)(mA & 1);

    float acc[4][4][4];
    #pragma unroll
    for (int mi = 0; mi < 4; mi++)
        #pragma unroll
        for (int ni = 0; ni < 4; ni++)
            #pragma unroll
            for (int q = 0; q < 4; q++) acc[mi][ni][q] = 0.f;

    const int KT = K >> 6;                     // 8
    auto produce = [&](int kt) {
        uint32_t base = sb + (uint32_t)(kt % NSTAGE) * STAGE_BYTES;
        int ko = kt << 6;
        #pragma unroll
        for (int i = 0; i < 4; i++) CP_ASYNC16(base + dA0 + i * 4096, pA0 + i * rStep + ko);
        #pragma unroll
        for (int i = 0; i < 4; i++) CP_ASYNC16(base + dB0 + i * 4096, pB0 + i * rStep + ko);
        CP_COMMIT();
    };

    produce(0);
    produce(1);
    #pragma unroll 1
    for (int kt = 0; kt < KT; kt++) {
        if (kt == KT - 1) { CP_WAIT(0); } else { CP_WAIT(1); }
        __syncthreads();
        if (kt + 2 < KT) produce(kt + 2);

        const uint32_t sBase = sb + (uint32_t)(kt % NSTAGE) * STAGE_BYTES;

        #pragma unroll
        for (int ks = 0; ks < 4; ks++) {
            uint32_t bf[4][2];
            #pragma unroll
            for (int p = 0; p < 2; p++) {
                uint32_t addr = sBase + bBase[p] + (((2u*ks + bHi) ^ bXor[p]) << 4);
                LDSM_X4(bf[2*p][0], bf[2*p][1], bf[2*p+1][0], bf[2*p+1][1], addr);
            }
            #pragma unroll
            for (int mi = 0; mi < 4; mi++) {
                uint32_t af[4];
                uint32_t addr = sBase + aBase[mi] + (((2u*ks + aHi) ^ aXor[mi]) << 4);
                LDSM_X4(af[0], af[1], af[2], af[3], addr);
                #pragma unroll
                for (int ni = 0; ni < 4; ni++)
                    mma_f16(acc[mi][ni], af, bf[ni]);
            }
        }
    }

    // ---- fused epilogue: fp16 reads, fp32 writes ----
    #pragma unroll
    for (int mi = 0; mi < 4; mi++) {
        #pragma unroll
        for (int rr = 0; rr < 2; rr++) {
            int row = m0 + wm * 64 + mi * 16 + g + rr * 8;
            #pragma unroll
            for (int ni = 0; ni < 4; ni++) {
                int col = n0 + wn * 32 + ni * 8 + tg * 2;
                size_t idx = (size_t)row * N_total + col;
                float v0 = acc[mi][ni][rr * 2 + 0];
                float v1 = acc[mi][ni][rr * 2 + 1];
                float2 y1 = __half22float2(*reinterpret_cast<const __half2*>(&Y1h[idx]));
                float2 y2 = __half22float2(*reinterpret_cast<const __half2*>(&Y2h[idx]));
                float2 w  = __half22float2(*reinterpret_cast<const __half2*>(&Wh[idx]));
                float ad0 = tanhf(Ad[col])     * 0.9f;
                float ad1 = tanhf(Ad[col + 1]) * 0.9f;
                float o0 = y1.x * (ad0 * w.x + v0) + y2.x;
                float o1 = y1.y * (ad1 * w.y + v1) + y2.y;
                *reinterpret_cast<float2*>(&out[idx]) = make_float2(o0, o1);
            }
        }
    }
}

// ---------------- host ------------------------------------------------------
extern "C" void kernel_launch(void* const* d_in, const int* in_sizes, int n_in,
                              void* d_out, int out_size)
{
    const float* w_prev = (const float*)d_in[0];   // [4096,2048]
    const float* z_t    = (const float*)d_in[1];   // [4096,2048]
    const float* c_t    = (const float*)d_in[2];   // [4096,1024]
    const float* A_diag = (const float*)d_in[3];   // [2048]
    const float* A_U    = (const float*)d_in[4];   // [2048,512]
    const float* A_V    = (const float*)d_in[5];   // [2048,512]
    const float* W_mod  = (const float*)d_in[6];   // [1024,2048]
    const float* b_mod  = (const float*)d_in[7];
    const float* W_B    = (const float*)d_in[8];   // [3072,2048]
    const float* b_B    = (const float*)d_in[9];
    float* out = (float*)d_out;                    // [4096,2048]
    (void)in_sizes; (void)n_in; (void)out_size;

    __half *CZ, *Wh, *AUh, *WmT, *WBT, *AVT, *T, *Y1, *Y2;
    cudaGetSymbolAddress((void**)&CZ,  g_CZ);
    cudaGetSymbolAddress((void**)&Wh,  g_Wh);
    cudaGetSymbolAddress((void**)&AUh, g_AUh);
    cudaGetSymbolAddress((void**)&WmT, g_WmT);
    cudaGetSymbolAddress((void**)&WBT, g_WBT);
    cudaGetSymbolAddress((void**)&AVT, g_AVT);
    cudaGetSymbolAddress((void**)&T,   g_T);
    cudaGetSymbolAddress((void**)&Y1,  g_Y1);
    cudaGetSymbolAddress((void**)&Y2,  g_Y2);

    cudaFuncSetAttribute(gemm_multi, cudaFuncAttributeMaxDynamicSharedMemorySize, SMEM_TOTAL);
    cudaFuncSetAttribute(gemm_g4,    cudaFuncAttributeMaxDynamicSharedMemorySize, SMEM_TOTAL);

    // pre-pass 1: all fp32->fp16 copies (c|z concat, w_prev, A_U)
    conv_all<<<21504, 256>>>((const float4*)c_t, (const float4*)z_t,
                             (const float4*)w_prev, (const float4*)A_U,
                             CZ, Wh, AUh);
    // pre-pass 2: three weight transposes
    transpose3<<<dim3(64, 96, 3), dim3(32, 8)>>>(W_B, W_mod, A_V, WBT, WmT, AVT);

    // merged G2 (z=0, longest K first) + G1 (z=1) + G3 (z=2)
    GCfg3 cf;
    cf.g0 = { CZ, WBT, b_B,   Y2, 3072, 2048, 3072, 4, 16 };  // G2 -> fp16
    cf.g1 = { CZ, WmT, b_mod, Y1, 1024, 2048, 3072, 3, 16 };  // G1 tanh -> fp16
    cf.g2 = { Wh, AVT, nullptr, T, 2048, 512, 2048, 1, 4 };   // G3 -> fp16
    gemm_multi<<<dim3(16, 32, 3), 128, SMEM_TOTAL>>>(cf);

    // G4 fused finale
    gemm_g4<<<dim3(16, 32), 256, SMEM_TOTAL>>>(T, AUh, Y1, Y2, Wh, A_diag, out);
}

// round 15
// speedup vs baseline: 2.8888x; 1.0073x over previous
#include <cuda_runtime.h>
#include <cuda_fp16.h>
#include <cstdint>
#include <cstddef>

// ============================================================================
// WaveSubsystem, sm_103 legacy-tensor path.
//   out = tanh(c@W_mod+b_mod) * (tanh(A_diag)*0.9*w + (w@A_V)@A_U^T) + [c|z]@W_B + b_B
// R14 = R13 + G4 epilogue fix: tanh hoisted to 8 tanh.approx per thread
// (was 64 precise tanhf), 3-stream loads batched for MLP; G1 uses tanh.approx.
// ============================================================================

#define BM 128
#define BN 128
#define STAGE_BYTES 32768          // A 16KB + B 16KB (fp16, BK=64)
#define NSTAGE 3
#define SMEM_TOTAL (STAGE_BYTES * NSTAGE)

// ---------------- scratch (__device__ globals; allocation-free rule) --------
__device__ __half g_CZ [4096ull*3072];   // fp16 [c|z]
__device__ __half g_Wh [4096ull*2048];   // fp16 w_prev
__device__ __half g_AUh[2048ull*512];    // fp16 A_U          [N,K]
__device__ __half g_WmT[2048ull*1024];   // fp16 W_mod^T      [N,K]
__device__ __half g_WBT[2048ull*3072];   // fp16 W_B^T        [N,K]
__device__ __half g_AVT[ 512ull*2048];   // fp16 A_V^T        [N,K]
__device__ __half g_T  [4096ull*512];    // fp16 w@A_V
__device__ __half g_Y1 [4096ull*2048];   // fp16 tanh(c@W_mod+b_mod)
__device__ __half g_Y2 [4096ull*2048];   // fp16 [c|z]@W_B + b_B

// ---------------- helpers ---------------------------------------------------
__device__ __forceinline__ uint32_t smem_u32(const void* p) {
    uint32_t a;
    asm("{ .reg .u64 t; cvta.to.shared.u64 t, %1; cvt.u32.u64 %0, t; }"
        : "=r"(a) : "l"(p));
    return a;
}
__device__ __forceinline__ float tanh_ap(float x) {
    float y;
    asm("tanh.approx.f32 %0, %1;" : "=f"(y) : "f"(x));
    return y;
}
#define CP_ASYNC16(dst, src) \
    asm volatile("cp.async.cg.shared.global [%0], [%1], 16;" :: "r"(dst), "l"(src))
#define CP_COMMIT()  asm volatile("cp.async.commit_group;" ::: "memory")
#define CP_WAIT(n)   asm volatile("cp.async.wait_group %0;" :: "n"(n) : "memory")

#define LDSM_X4(r0, r1, r2, r3, addr) \
    asm volatile("ldmatrix.sync.aligned.m8n8.x4.shared.b16 {%0,%1,%2,%3}, [%4];" \
        : "=r"(r0), "=r"(r1), "=r"(r2), "=r"(r3) : "r"(addr))

__device__ __forceinline__ void mma_f16(float c[4],
                                        const uint32_t a[4],
                                        const uint32_t b[2]) {
    asm volatile(
        "mma.sync.aligned.m16n8k16.row.col.f32.f16.f16.f32 "
        "{%0,%1,%2,%3}, {%4,%5,%6,%7}, {%8,%9}, {%0,%1,%2,%3};"
        : "+f"(c[0]), "+f"(c[1]), "+f"(c[2]), "+f"(c[3])
        : "r"(a[0]), "r"(a[1]), "r"(a[2]), "r"(a[3]),
          "r"(b[0]), "r"(b[1]));
}

// ---------------- pre-pass 1: all fp32->fp16 copies (with concat restride) --
__global__ void conv_all(const float4* __restrict__ c, const float4* __restrict__ z,
                         const float4* __restrict__ w, const float4* __restrict__ au,
                         __half* __restrict__ CZ, __half* __restrict__ Wh,
                         __half* __restrict__ AUh) {
    int i = blockIdx.x * blockDim.x + threadIdx.x;
    const float4* in; __half* out; int n4, os, off;
    if (i < 1048576)      { in = c;  out = CZ;  n4 = 256; os = 3072; off = 0;    }
    else if (i < 3145728) { i -= 1048576; in = z;  out = CZ;  n4 = 512; os = 3072; off = 1024; }
    else if (i < 5242880) { i -= 3145728; in = w;  out = Wh;  n4 = 512; os = 2048; off = 0;    }
    else                  { i -= 5242880; if (i >= 262144) return;
                            in = au; out = AUh; n4 = 128; os = 512;  off = 0;    }
    int m = i / n4, k = i - m * n4;
    float4 v = in[i];
    __half2 h0 = __floats2half2_rn(v.x, v.y);
    __half2 h1 = __floats2half2_rn(v.z, v.w);
    uint2 r = make_uint2(*(uint32_t*)&h0, *(uint32_t*)&h1);
    *reinterpret_cast<uint2*>(&out[(size_t)m * os + off + 4 * k]) = r;
}

// ---------------- pre-pass 2: three transposes (fp32 [R,C] -> fp16 [C,R]) ---
__global__ void transpose3(const float* __restrict__ wb, const float* __restrict__ wm,
                           const float* __restrict__ av, __half* __restrict__ WBT,
                           __half* __restrict__ WmT, __half* __restrict__ AVT) {
    const float* in; __half* out; int R, C, gx, gy;
    if (blockIdx.z == 0)      { in = wb; out = WBT; R = 3072; C = 2048; gx = 64; gy = 96; }
    else if (blockIdx.z == 1) { in = wm; out = WmT; R = 1024; C = 2048; gx = 64; gy = 32; }
    else                      { in = av; out = AVT; R = 2048; C = 512;  gx = 16; gy = 64; }
    if ((int)blockIdx.x >= gx || (int)blockIdx.y >= gy) return;
    __shared__ float t[32][33];
    int x  = blockIdx.x * 32 + threadIdx.x;
    int y0 = blockIdx.y * 32;
    #pragma unroll
    for (int j = 0; j < 32; j += 8)
        t[threadIdx.y + j][threadIdx.x] = in[(size_t)(y0 + threadIdx.y + j) * C + x];
    __syncthreads();
    int ox  = y0 + threadIdx.x;
    int oy0 = blockIdx.x * 32;
    #pragma unroll
    for (int j = 0; j < 32; j += 8)
        out[(size_t)(oy0 + threadIdx.y + j) * R + ox] =
            __float2half_rn(t[threadIdx.x][threadIdx.y + j]);
}

// ---------------- merged GEMM G1/G2/G3: C = A @ B^T, fp16 stores ------------
// smem per stage: 128B rows (64 halves), 16B-granule xor swizzle. 4 warps 2x2.
// epi: 1 = plain->fp16   3 = tanh(v+bias)->fp16   4 = (v+bias)->fp16
struct GCfg {
    const __half* A; const __half* B;
    const float* bias; __half* C;
    int K, N, lda, epi, gx;
};
struct GCfg3 { GCfg g0, g1, g2; };

__global__ __launch_bounds__(128, 2)
void gemm_multi(GCfg3 cfgs)
{
    GCfg cf = cfgs.g0;
    if (blockIdx.z == 1) cf = cfgs.g1;
    else if (blockIdx.z == 2) cf = cfgs.g2;
    if ((int)blockIdx.x >= cf.gx) return;

    extern __shared__ __align__(128) char sm[];
    const uint32_t sb = smem_u32(sm);
    const int tid  = threadIdx.x;
    const int warp = tid >> 5, lane = tid & 31;
    const int wm = warp & 1, wn = warp >> 1;       // 2x2 warps, 64x64 tiles
    const int g  = lane >> 2, tg = lane & 3;
    const int m0 = blockIdx.y * BM, n0 = blockIdx.x * BN;
    const int K = cf.K, lda = cf.lda, N_total = cf.N;

    const int r0 = tid >> 3, jg = tid & 7;
    const __half* pA0 = cf.A + (size_t)(m0 + r0) * lda + jg * 8;
    const __half* pB0 = cf.B + (size_t)(n0 + r0) * K + jg * 8;
    const size_t aStep = (size_t)16 * lda;
    const size_t bStep = (size_t)16 * K;
    const uint32_t dA0 = r0 * 128 + ((jg ^ (r0 & 7)) << 4);
    const uint32_t dB0 = 16384u + dA0;

    const int mA = lane >> 3, iA = lane & 7;
    uint32_t aBase[4], aXor[4];
    #pragma unroll
    for (int mi = 0; mi < 4; mi++) {
        int row = wm * 64 + mi * 16 + (mA & 1) * 8 + iA;
        aBase[mi] = (uint32_t)row * 128;
        aXor[mi]  = (uint32_t)(row & 7);
    }
    const uint32_t aHi = (uint32_t)(mA >> 1);
    uint32_t bBase[4], bXor[4];
    #pragma unroll
    for (int p = 0; p < 4; p++) {
        int row = wn * 64 + p * 16 + ((mA >> 1) << 3) + iA;
        bBase[p] = 16384u + (uint32_t)row * 128;
        bXor[p]  = (uint32_t)(row & 7);
    }
    const uint32_t bHi = (uint32_t)(mA & 1);

    float acc[4][8][4];
    #pragma unroll
    for (int mi = 0; mi < 4; mi++)
        #pragma unroll
        for (int ni = 0; ni < 8; ni++)
            #pragma unroll
            for (int q = 0; q < 4; q++) acc[mi][ni][q] = 0.f;

    const int KT = K >> 6;                     // BK = 64
    auto produce = [&](int kt) {
        uint32_t base = sb + (uint32_t)(kt % NSTAGE) * STAGE_BYTES;
        int ko = kt << 6;
        #pragma unroll
        for (int i = 0; i < 8; i++) CP_ASYNC16(base + dA0 + i * 2048, pA0 + i * aStep + ko);
        #pragma unroll
        for (int i = 0; i < 8; i++) CP_ASYNC16(base + dB0 + i * 2048, pB0 + i * bStep + ko);
        CP_COMMIT();
    };

    produce(0);
    produce(1);
    #pragma unroll 1
    for (int kt = 0; kt < KT; kt++) {
        if (kt == KT - 1) { CP_WAIT(0); } else { CP_WAIT(1); }
        __syncthreads();
        if (kt + 2 < KT) produce(kt + 2);

        const uint32_t sBase = sb + (uint32_t)(kt % NSTAGE) * STAGE_BYTES;

        #pragma unroll
        for (int ks = 0; ks < 4; ks++) {
            uint32_t bf[8][2];
            #pragma unroll
            for (int p = 0; p < 4; p++) {
                uint32_t addr = sBase + bBase[p] + (((2u*ks + bHi) ^ bXor[p]) << 4);
                LDSM_X4(bf[2*p][0], bf[2*p][1], bf[2*p+1][0], bf[2*p+1][1], addr);
            }
            #pragma unroll
            for (int mi = 0; mi < 4; mi++) {
                uint32_t af[4];
                uint32_t addr = sBase + aBase[mi] + (((2u*ks + aHi) ^ aXor[mi]) << 4);
                LDSM_X4(af[0], af[1], af[2], af[3], addr);
                #pragma unroll
                for (int ni = 0; ni < 8; ni++)
                    mma_f16(acc[mi][ni], af, bf[ni]);
            }
        }
    }

    // ---- epilogue: fp16 stores ----
    const int epi = cf.epi;
    #pragma unroll
    for (int mi = 0; mi < 4; mi++) {
        #pragma unroll
        for (int rr = 0; rr < 2; rr++) {
            int row = m0 + wm * 64 + mi * 16 + g + rr * 8;
            #pragma unroll
            for (int ni = 0; ni < 8; ni++) {
                int col = n0 + wn * 64 + ni * 8 + tg * 2;
                size_t idx = (size_t)row * N_total + col;
                float v0 = acc[mi][ni][rr * 2 + 0];
                float v1 = acc[mi][ni][rr * 2 + 1];
                if (epi == 3) {
                    v0 = tanh_ap(v0 + cf.bias[col]); v1 = tanh_ap(v1 + cf.bias[col + 1]);
                } else if (epi == 4) {
                    v0 += cf.bias[col]; v1 += cf.bias[col + 1];
                }
                __half2 h = __floats2half2_rn(v0, v1);
                *reinterpret_cast<__half2*>(&cf.C[idx]) = h;
            }
        }
    }
}

// ---------------- G4: out = Y1 * (ad*w + T@AU^T) + Y2 (all fp16 streams) ----
// 256 threads, 8 warps (2x4), warp tile 64x32. CTA 128x128, K=512.
__global__ __launch_bounds__(256, 2)
void gemm_g4(const __half* __restrict__ A,   // T  [4096,512]
             const __half* __restrict__ B,   // AUh [2048,512]
             const __half* __restrict__ Y1h,
             const __half* __restrict__ Y2h,
             const __half* __restrict__ Wh,
             const float* __restrict__ Ad,
             float* __restrict__ out)
{
    extern __shared__ __align__(128) char sm[];
    const uint32_t sb = smem_u32(sm);
    const int tid  = threadIdx.x;
    const int warp = tid >> 5, lane = tid & 31;
    const int wm = warp & 1, wn = warp >> 1;       // 2x4 warps, 64x32 tiles
    const int g  = lane >> 2, tg = lane & 3;
    const int m0 = blockIdx.y * BM, n0 = blockIdx.x * BN;
    const int K = 512, N_total = 2048;

    const int r0 = tid >> 3, jg = tid & 7;
    const __half* pA0 = A + (size_t)(m0 + r0) * K + jg * 8;
    const __half* pB0 = B + (size_t)(n0 + r0) * K + jg * 8;
    const size_t rStep = (size_t)32 * K;
    const uint32_t dA0 = r0 * 128 + ((jg ^ (r0 & 7)) << 4);
    const uint32_t dB0 = 16384u + dA0;

    const int mA = lane >> 3, iA = lane & 7;
    uint32_t aBase[4], aXor[4];
    #pragma unroll
    for (int mi = 0; mi < 4; mi++) {
        int row = wm * 64 + mi * 16 + (mA & 1) * 8 + iA;
        aBase[mi] = (uint32_t)row * 128;
        aXor[mi]  = (uint32_t)(row & 7);
    }
    const uint32_t aHi = (uint32_t)(mA >> 1);
    uint32_t bBase[2], bXor[2];
    #pragma unroll
    for (int p = 0; p < 2; p++) {
        int row = wn * 32 + p * 16 + ((mA >> 1) << 3) + iA;
        bBase[p] = 16384u + (uint32_t)row * 128;
        bXor[p]  = (uint32_t)(row & 7);
    }
    const uint32_t bHi = (uint32_t)(mA & 1);

    float acc[4][4][4];
    #pragma unroll
    for (int mi = 0; mi < 4; mi++)
        #pragma unroll
        for (int ni = 0; ni < 4; ni++)
            #pragma unroll
            for (int q = 0; q < 4; q++) acc[mi][ni][q] = 0.f;

    const int KT = K >> 6;                     // 8
    auto produce = [&](int kt) {
        uint32_t base = sb + (uint32_t)(kt % NSTAGE) * STAGE_BYTES;
        int ko = kt << 6;
        #pragma unroll
        for (int i = 0; i < 4; i++) CP_ASYNC16(base + dA0 + i * 4096, pA0 + i * rStep + ko);
        #pragma unroll
        for (int i = 0; i < 4; i++) CP_ASYNC16(base + dB0 + i * 4096, pB0 + i * rStep + ko);
        CP_COMMIT();
    };

    produce(0);
    produce(1);
    #pragma unroll 1
    for (int kt = 0; kt < KT; kt++) {
        if (kt == KT - 1) { CP_WAIT(0); } else { CP_WAIT(1); }
        __syncthreads();
        if (kt + 2 < KT) produce(kt + 2);

        const uint32_t sBase = sb + (uint32_t)(kt % NSTAGE) * STAGE_BYTES;

        #pragma unroll
        for (int ks = 0; ks < 4; ks++) {
            uint32_t bf[4][2];
            #pragma unroll
            for (int p = 0; p < 2; p++) {
                uint32_t addr = sBase + bBase[p] + (((2u*ks + bHi) ^ bXor[p]) << 4);
                LDSM_X4(bf[2*p][0], bf[2*p][1], bf[2*p+1][0], bf[2*p+1][1], addr);
            }
            #pragma unroll
            for (int mi = 0; mi < 4; mi++) {
                uint32_t af[4];
                uint32_t addr = sBase + aBase[mi] + (((2u*ks + aHi) ^ aXor[mi]) << 4);
                LDSM_X4(af[0], af[1], af[2], af[3], addr);
                #pragma unroll
                for (int ni = 0; ni < 4; ni++)
                    mma_f16(acc[mi][ni], af, bf[ni]);
            }
        }
    }

    // ---- fused epilogue ----
    // precompute the 8 distinct a_diag values per thread ONCE (was 64 tanhf)
    float adv[4][2];
    #pragma unroll
    for (int ni = 0; ni < 4; ni++) {
        int col = n0 + wn * 32 + ni * 8 + tg * 2;
        adv[ni][0] = tanh_ap(Ad[col])     * 0.9f;
        adv[ni][1] = tanh_ap(Ad[col + 1]) * 0.9f;
    }
    #pragma unroll
    for (int mi = 0; mi < 4; mi++) {
        #pragma unroll
        for (int rr = 0; rr < 2; rr++) {
            int row = m0 + wm * 64 + mi * 16 + g + rr * 8;
            size_t rbase = (size_t)row * N_total;
            // batch all 12 loads first (MLP), then compute
            float2 y1v[4], y2v[4], wv[4];
            #pragma unroll
            for (int ni = 0; ni < 4; ni++) {
                int col = n0 + wn * 32 + ni * 8 + tg * 2;
                y1v[ni] = __half22float2(*reinterpret_cast<const __half2*>(&Y1h[rbase + col]));
                y2v[ni] = __half22float2(*reinterpret_cast<const __half2*>(&Y2h[rbase + col]));
                wv[ni]  = __half22float2(*reinterpret_cast<const __half2*>(&Wh[rbase + col]));
            }
            #pragma unroll
            for (int ni = 0; ni < 4; ni++) {
                int col = n0 + wn * 32 + ni * 8 + tg * 2;
                float v0 = acc[mi][ni][rr * 2 + 0];
                float v1 = acc[mi][ni][rr * 2 + 1];
                float o0 = y1v[ni].x * (adv[ni][0] * wv[ni].x + v0) + y2v[ni].x;
                float o1 = y1v[ni].y * (adv[ni][1] * wv[ni].y + v1) + y2v[ni].y;
                *reinterpret_cast<float2*>(&out[rbase + col]) = make_float2(o0, o1);
            }
        }
    }
}

// ---------------- host ------------------------------------------------------
extern "C" void kernel_launch(void* const* d_in, const int* in_sizes, int n_in,
                              void* d_out, int out_size)
{
    const float* w_prev = (const float*)d_in[0];   // [4096,2048]
    const float* z_t    = (const float*)d_in[1];   // [4096,2048]
    const float* c_t    = (const float*)d_in[2];   // [4096,1024]
    const float* A_diag = (const float*)d_in[3];   // [2048]
    const float* A_U    = (const float*)d_in[4];   // [2048,512]
    const float* A_V    = (const float*)d_in[5];   // [2048,512]
    const float* W_mod  = (const float*)d_in[6];   // [1024,2048]
    const float* b_mod  = (const float*)d_in[7];
    const float* W_B    = (const float*)d_in[8];   // [3072,2048]
    const float* b_B    = (const float*)d_in[9];
    float* out = (float*)d_out;                    // [4096,2048]
    (void)in_sizes; (void)n_in; (void)out_size;

    __half *CZ, *Wh, *AUh, *WmT, *WBT, *AVT, *T, *Y1, *Y2;
    cudaGetSymbolAddress((void**)&CZ,  g_CZ);
    cudaGetSymbolAddress((void**)&Wh,  g_Wh);
    cudaGetSymbolAddress((void**)&AUh, g_AUh);
    cudaGetSymbolAddress((void**)&WmT, g_WmT);
    cudaGetSymbolAddress((void**)&WBT, g_WBT);
    cudaGetSymbolAddress((void**)&AVT, g_AVT);
    cudaGetSymbolAddress((void**)&T,   g_T);
    cudaGetSymbolAddress((void**)&Y1,  g_Y1);
    cudaGetSymbolAddress((void**)&Y2,  g_Y2);

    cudaFuncSetAttribute(gemm_multi, cudaFuncAttributeMaxDynamicSharedMemorySize, SMEM_TOTAL);
    cudaFuncSetAttribute(gemm_g4,    cudaFuncAttributeMaxDynamicSharedMemorySize, SMEM_TOTAL);

    // pre-pass 1: all fp32->fp16 copies (c|z concat, w_prev, A_U)
    conv_all<<<21504, 256>>>((const float4*)c_t, (const float4*)z_t,
                             (const float4*)w_prev, (const float4*)A_U,
                             CZ, Wh, AUh);
    // pre-pass 2: three weight transposes
    transpose3<<<dim3(64, 96, 3), dim3(32, 8)>>>(W_B, W_mod, A_V, WBT, WmT, AVT);

    // merged G2 (z=0, longest K first) + G1 (z=1) + G3 (z=2)
    GCfg3 cf;
    cf.g0 = { CZ, WBT, b_B,   Y2, 3072, 2048, 3072, 4, 16 };  // G2 -> fp16
    cf.g1 = { CZ, WmT, b_mod, Y1, 1024, 2048, 3072, 3, 16 };  // G1 tanh -> fp16
    cf.g2 = { Wh, AVT, nullptr, T, 2048, 512, 2048, 1, 4 };   // G3 -> fp16
    gemm_multi<<<dim3(16, 32, 3), 128, SMEM_TOTAL>>>(cf);

    // G4 fused finale
    gemm_g4<<<dim3(16, 32), 256, SMEM_TOTAL>>>(T, AUh, Y1, Y2, Wh, A_diag, out);
}